// round 11
// baseline (speedup 1.0000x reference)
#include <cuda_runtime.h>
#include <cuda_bf16.h>
#include <math.h>
#include <stdint.h>

// Problem constants
#define B_     2
#define N_     1024
#define DIM_   1024
#define HEADS_ 8
#define HD_    128
#define L_     4096   // m * nc
#define M_DOCS 4

// ---------------------------------------------------------------------------
// Scratch (__device__ globals; allocation-free rule)
// ---------------------------------------------------------------------------
// split-bf16 operand buffers for GEMM inputs
__device__ __nv_bfloat16 g_xh [(B_*N_) * DIM_];
__device__ __nv_bfloat16 g_xl [(B_*N_) * DIM_];
__device__ __nv_bfloat16 g_ch [(B_*L_) * DIM_];
__device__ __nv_bfloat16 g_cl [(B_*L_) * DIM_];
__device__ __nv_bfloat16 g_oh [(B_*N_) * DIM_];   // attn output, split hi
__device__ __nv_bfloat16 g_ol [(B_*N_) * DIM_];   // attn output, split lo
// weights transposed to [N,K]
__device__ __nv_bfloat16 g_wqh [DIM_ * DIM_];
__device__ __nv_bfloat16 g_wql [DIM_ * DIM_];
__device__ __nv_bfloat16 g_wkvh[(2*DIM_) * DIM_];
__device__ __nv_bfloat16 g_wkvl[(2*DIM_) * DIM_];
__device__ __nv_bfloat16 g_woh [DIM_ * DIM_];
__device__ __nv_bfloat16 g_wol [DIM_ * DIM_];

// attention operands (produced directly by GEMM epilogues)
__device__ __nv_bfloat16 g_qb [(B_*N_) * DIM_];           // Q plain bf16
__device__ __nv_bfloat16 g_kb [(B_*L_) * DIM_];           // K plain bf16
__device__ __nv_bfloat16 g_vth[B_*HEADS_*HD_ * L_];       // V^T hi  [bh*128+d][key]
__device__ __nv_bfloat16 g_vtl[B_*HEADS_*HD_ * L_];       // V^T lo

// ---------------------------------------------------------------------------
// PTX helpers — ONLY non-'a' features (compute_103 PTX: no tcgen05).
// ---------------------------------------------------------------------------
#define CP_ASYNC16(dst, src) \
    asm volatile("cp.async.cg.shared.global [%0], [%1], 16;\n" \
                 :: "r"(dst), "l"(src) : "memory")
#define CP_ASYNC_COMMIT()  asm volatile("cp.async.commit_group;\n" ::: "memory")
#define CP_ASYNC_WAIT1()   asm volatile("cp.async.wait_group 1;\n" ::: "memory")
#define CP_ASYNC_WAIT0()   asm volatile("cp.async.wait_group 0;\n" ::: "memory")

#define LDSM_X4(r0, r1, r2, r3, a) \
    asm volatile("ldmatrix.sync.aligned.m8n8.x4.shared.b16 {%0,%1,%2,%3}, [%4];" \
                 : "=r"(r0), "=r"(r1), "=r"(r2), "=r"(r3) : "r"(a))

__device__ __forceinline__ uint32_t smem_u32(const void* p) {
    uint32_t a;
    asm("{ .reg .u64 t; cvta.to.shared.u64 t, %1; cvt.u32.u64 %0, t; }"
        : "=r"(a) : "l"(p));
    return a;
}

// D += A @ B^T : m16n8k16, bf16 in, fp32 accum (layout validated R8/R10)
__device__ __forceinline__ void mma16816(float* d, const uint32_t* a,
                                         const uint32_t* b) {
    asm volatile(
        "mma.sync.aligned.m16n8k16.row.col.f32.bf16.bf16.f32 "
        "{%0,%1,%2,%3}, {%4,%5,%6,%7}, {%8,%9}, {%0,%1,%2,%3};"
        : "+f"(d[0]), "+f"(d[1]), "+f"(d[2]), "+f"(d[3])
        : "r"(a[0]), "r"(a[1]), "r"(a[2]), "r"(a[3]), "r"(b[0]), "r"(b[1]));
}

__device__ __forceinline__ uint32_t pack_bf16(float a, float b) {
    __nv_bfloat162 t = __float22bfloat162_rn(make_float2(a, b));
    return *(uint32_t*)&t;
}

// ---------------------------------------------------------------------------
// Conversion kernels (inputs + weights only; everything else fused)
// ---------------------------------------------------------------------------
__global__ void conv_split(const float* __restrict__ A,
                           __nv_bfloat16* __restrict__ Ah,
                           __nv_bfloat16* __restrict__ Al, int total)
{
    int i = blockIdx.x * blockDim.x + threadIdx.x;
    if (i >= total) return;
    float v = A[i];
    __nv_bfloat16 hi = __float2bfloat16(v);
    Ah[i] = hi;
    Al[i] = __float2bfloat16(v - __bfloat162float(hi));
}

// W[K,N] fp32 -> Wh/Wl [N,K] bf16 (transpose + split)
__global__ void conv_w_t(const float* __restrict__ W,
                         __nv_bfloat16* __restrict__ Wh,
                         __nv_bfloat16* __restrict__ Wl, int K, int N)
{
    __shared__ float t[32][33];
    int k0 = blockIdx.y * 32, n0 = blockIdx.x * 32;
    int tx = threadIdx.x, ty = threadIdx.y;
    #pragma unroll
    for (int i = 0; i < 32; i += 8)
        t[ty + i][tx] = W[(size_t)(k0 + ty + i) * N + n0 + tx];
    __syncthreads();
    #pragma unroll
    for (int i = 0; i < 32; i += 8) {
        float v = t[tx][ty + i];
        __nv_bfloat16 hi = __float2bfloat16(v);
        size_t o = (size_t)(n0 + ty + i) * K + k0 + tx;
        Wh[o] = hi;
        Wl[o] = __float2bfloat16(v - __bfloat162float(hi));
    }
}

// ---------------------------------------------------------------------------
// mma.sync split-bf16 GEMM with ldmatrix + fused epilogues.
//   mode 0: C fp32 = acc + bias
//   mode 1: Cb bf16 plain (Q path)
//   mode 2: KV path — col<1024: kb plain bf16; col>=1024: V^T split to vth/vtl
// ---------------------------------------------------------------------------
#define GM_BM  128
#define GM_BN  128
#define GM_BK  64
#define GM_LDA 72
#define GM_STAGE_ELEMS ((GM_BM + GM_BN) * GM_LDA)
#define GM_SMEM_DYN (2 * GM_STAGE_ELEMS * 2)

__global__ __launch_bounds__(256, 2)
void gemm_mma(const __nv_bfloat16* __restrict__ Ah,
              const __nv_bfloat16* __restrict__ Al,
              const __nv_bfloat16* __restrict__ Bh,
              const __nv_bfloat16* __restrict__ Bl,
              const float* __restrict__ bias, float* __restrict__ C,
              __nv_bfloat16* __restrict__ Cb,
              __nv_bfloat16* __restrict__ vth,
              __nv_bfloat16* __restrict__ vtl,
              int M, int N, int K, int mode)
{
    extern __shared__ __align__(16) __nv_bfloat16 dsm[];

    const int tid   = threadIdx.x;
    const int wid   = tid >> 5;
    const int lane  = tid & 31;
    const int g     = lane >> 2;
    const int t4    = lane & 3;
    const int warpM = wid & 3;
    const int warpN = wid >> 2;
    const int m0 = blockIdx.y * GM_BM;
    const int n0 = blockIdx.x * GM_BN;
    const int KB = K * 2;
    const int kchunks = K / GM_BK;
    const int NCHUNK = 3 * kchunks;

    const uint32_t smem_base = smem_u32(dsm);

    // ldmatrix lane offsets (bytes, relative to tile base)
    const uint32_t aOff = (uint32_t)(warpM * 32 + (lane & 15)) * (GM_LDA * 2)
                        + ((lane >> 4) << 3) * 2;
    const uint32_t bOff = (uint32_t)(warpN * 64 + ((lane & 16) >> 1) + (lane & 7))
                        * (GM_LDA * 2) + ((lane & 8) ? 16 : 0);

    float acc[2][8][4];
    #pragma unroll
    for (int mi = 0; mi < 2; mi++)
        #pragma unroll
        for (int ni = 0; ni < 8; ni++)
            #pragma unroll
            for (int r = 0; r < 4; r++) acc[mi][ni][r] = 0.f;

    auto load_tile = [&](int s, int c) {
        int pass = c / kchunks;
        int kc   = c - pass * kchunks;
        const char* Asrc = (const char*)((pass < 2) ? Ah : Al)
                         + (size_t)m0 * KB + (size_t)kc * (GM_BK * 2);
        const char* Bsrc = (const char*)((pass == 1) ? Bl : Bh)
                         + (size_t)n0 * KB + (size_t)kc * (GM_BK * 2);
        uint32_t As = smem_base + s * (GM_STAGE_ELEMS * 2);
        uint32_t Bs = As + GM_BM * GM_LDA * 2;
        #pragma unroll
        for (int i = 0; i < 8; i++) {
            int u = tid + i * 256;
            if (i < 4) {
                int row = u >> 3, ch = u & 7;
                CP_ASYNC16(As + row * (GM_LDA * 2) + ch * 16,
                           Asrc + (size_t)row * KB + ch * 16);
            } else {
                int v = u - 1024;
                int row = v >> 3, ch = v & 7;
                CP_ASYNC16(Bs + row * (GM_LDA * 2) + ch * 16,
                           Bsrc + (size_t)row * KB + ch * 16);
            }
        }
        CP_ASYNC_COMMIT();
    };

    load_tile(0, 0);

    for (int c = 0; c < NCHUNK; c++) {
        if (c + 1 < NCHUNK) {
            load_tile((c + 1) & 1, c + 1);
            CP_ASYNC_WAIT1();
        } else {
            CP_ASYNC_WAIT0();
        }
        __syncthreads();

        uint32_t As = smem_base + (c & 1) * (GM_STAGE_ELEMS * 2);
        uint32_t Bs = As + GM_BM * GM_LDA * 2;
        uint32_t aAddr = As + aOff;
        uint32_t bAddr = Bs + bOff;

        #pragma unroll
        for (int kk = 0; kk < GM_BK; kk += 16) {
            uint32_t af[2][4], bfr[8][2];
            #pragma unroll
            for (int mi = 0; mi < 2; mi++)
                LDSM_X4(af[mi][0], af[mi][1], af[mi][2], af[mi][3],
                        aAddr + kk * 2 + mi * 16 * (GM_LDA * 2));
            #pragma unroll
            for (int pr = 0; pr < 4; pr++)
                LDSM_X4(bfr[2*pr][0], bfr[2*pr][1], bfr[2*pr+1][0], bfr[2*pr+1][1],
                        bAddr + kk * 2 + pr * 16 * (GM_LDA * 2));
            #pragma unroll
            for (int mi = 0; mi < 2; mi++)
                #pragma unroll
                for (int ni = 0; ni < 8; ni++)
                    mma16816(acc[mi][ni], af[mi], bfr[ni]);
        }
        __syncthreads();
    }

    // fused epilogue
    #pragma unroll
    for (int mi = 0; mi < 2; mi++) {
        int rowA = m0 + warpM * 32 + mi * 16 + g;
        #pragma unroll
        for (int ni = 0; ni < 8; ni++) {
            int col = n0 + warpN * 64 + ni * 8 + 2 * t4;
            #pragma unroll
            for (int half = 0; half < 2; half++) {
                int row = rowA + half * 8;
                float v0 = acc[mi][ni][half * 2 + 0];
                float v1 = acc[mi][ni][half * 2 + 1];
                if (mode == 0) {
                    *(float2*)(C + (size_t)row * N + col) =
                        make_float2(v0 + bias[col], v1 + bias[col + 1]);
                } else if (mode == 1) {
                    uint32_t p = pack_bf16(v0, v1);
                    *(uint32_t*)(Cb + (size_t)row * N + col) = p;
                } else {
                    if (col < 1024) {
                        uint32_t p = pack_bf16(v0, v1);
                        *(uint32_t*)(Cb + (size_t)row * 1024 + col) = p;
                    } else {
                        int bb = row >> 12, key = row & (L_ - 1);
                        int c2 = col - 1024;
                        size_t off = ((size_t)((bb << 3) + (c2 >> 7)) * HD_
                                      + (c2 & 127)) * L_ + key;
                        __nv_bfloat16 h0 = __float2bfloat16(v0);
                        __nv_bfloat16 h1 = __float2bfloat16(v1);
                        vth[off]      = h0;
                        vtl[off]      = __float2bfloat16(v0 - __bfloat162float(h0));
                        vth[off + L_] = h1;
                        vtl[off + L_] = __float2bfloat16(v1 - __bfloat162float(h1));
                    }
                }
            }
        }
    }
}

// ---------------------------------------------------------------------------
// Flash attention on mma.sync, ldmatrix fragments, double-buffered K/V.
// CTA = (128-query tile, head, batch); 256 threads = 8 warps (16 q-rows each).
// QK^T plain bf16; P·V split x split (3 passes); O in 64 fp32 regs.
// Epilogue writes split-bf16 (oh/ol) directly.
// ---------------------------------------------------------------------------
#define AT_LDQ 136
#define AT_LDK 136
#define AT_LDV 72
#define AT_ST_ELEMS (64*AT_LDK + 2*128*AT_LDV)               // 27136
#define AT_SMEM ((128*AT_LDQ + 2*AT_ST_ELEMS) * 2)           // 143360 B

__global__ __launch_bounds__(256, 1)
void ca_attn_mma(const __nv_bfloat16* __restrict__ qb,
                 const __nv_bfloat16* __restrict__ kb,
                 const __nv_bfloat16* __restrict__ vth,
                 const __nv_bfloat16* __restrict__ vtl,
                 const float* __restrict__ sims,
                 const float* __restrict__ beta_p,
                 __nv_bfloat16* __restrict__ Oh,
                 __nv_bfloat16* __restrict__ Ol)
{
    extern __shared__ __align__(16) __nv_bfloat16 smattn[];
    const uint32_t sQ = smem_u32(smattn);

    const int qt = blockIdx.x, h = blockIdx.y, b = blockIdx.z;
    const int tid = threadIdx.x, wid = tid >> 5, lane = tid & 31;
    const int g = lane >> 2, t4 = lane & 3;
    const float beta = beta_p[0];
    const int qrow0 = b * N_ + qt * 128;
    const size_t vbase = (size_t)(b * HEADS_ + h) * HD_ * (size_t)L_;

    // ldmatrix lane offsets
    const uint32_t qOff = (uint32_t)(wid * 16 + (lane & 15)) * (AT_LDQ * 2)
                        + ((lane >> 4) << 3) * 2;
    const uint32_t kOff = (uint32_t)(((lane & 16) >> 1) + (lane & 7)) * (AT_LDK * 2)
                        + ((lane & 8) ? 16 : 0);
    const uint32_t vOff = (uint32_t)(((lane & 16) >> 1) + (lane & 7)) * (AT_LDV * 2)
                        + ((lane & 8) ? 16 : 0);

    // Q tile: 128 rows x 256 B (own cp.async group)
    #pragma unroll
    for (int i = 0; i < 8; i++) {
        int u = tid + i * 256, r = u >> 4, ch = u & 15;
        CP_ASYNC16(sQ + r * (AT_LDQ * 2) + ch * 16,
                   (const char*)qb + ((size_t)(qrow0 + r) * DIM_ + h * HD_) * 2 + ch * 16);
    }
    CP_ASYNC_COMMIT();

    auto stage_base = [&](int s) -> uint32_t {
        return sQ + 128 * AT_LDQ * 2 + s * (AT_ST_ELEMS * 2);
    };
    auto load_kv = [&](int s, int kt) {
        uint32_t sK  = stage_base(s);
        uint32_t sVh = sK + 64 * AT_LDK * 2;
        uint32_t sVl = sVh + 128 * AT_LDV * 2;
        const size_t krow0 = (size_t)(b * L_ + kt * 64);
        #pragma unroll
        for (int i = 0; i < 4; i++) {
            int u = tid + i * 256, r = u >> 4, ch = u & 15;
            CP_ASYNC16(sK + r * (AT_LDK * 2) + ch * 16,
                       (const char*)kb + ((krow0 + r) * DIM_ + h * HD_) * 2 + ch * 16);
        }
        #pragma unroll
        for (int i = 0; i < 4; i++) {
            int u = tid + i * 256, r = u >> 3, ch = u & 7;
            size_t src = (vbase + (size_t)r * L_ + kt * 64) * 2 + ch * 16;
            CP_ASYNC16(sVh + r * (AT_LDV * 2) + ch * 16, (const char*)vth + src);
        }
        #pragma unroll
        for (int i = 0; i < 4; i++) {
            int u = tid + i * 256, r = u >> 3, ch = u & 7;
            size_t src = (vbase + (size_t)r * L_ + kt * 64) * 2 + ch * 16;
            CP_ASYNC16(sVl + r * (AT_LDV * 2) + ch * 16, (const char*)vtl + src);
        }
        CP_ASYNC_COMMIT();
    };

    load_kv(0, 0);

    float o[16][4];
    #pragma unroll
    for (int nj = 0; nj < 16; nj++)
        #pragma unroll
        for (int r = 0; r < 4; r++) o[nj][r] = 0.f;
    float m0r = -3.0e38f, m1r = -3.0e38f, l0r = 0.f, l1r = 0.f;

    for (int kt = 0; kt < 64; kt++) {
        if (kt + 1 < 64) {
            load_kv((kt + 1) & 1, kt + 1);
            CP_ASYNC_WAIT1();
        } else {
            CP_ASYNC_WAIT0();
        }
        __syncthreads();

        uint32_t sK  = stage_base(kt & 1);
        uint32_t sVh = sK + 64 * AT_LDK * 2;
        uint32_t sVl = sVh + 128 * AT_LDV * 2;

        // ---- S = Q @ K^T ----
        float s[8][4];
        #pragma unroll
        for (int nj = 0; nj < 8; nj++)
            #pragma unroll
            for (int r = 0; r < 4; r++) s[nj][r] = 0.f;

        #pragma unroll
        for (int kk = 0; kk < 128; kk += 16) {
            uint32_t af[4], bfr[8][2];
            LDSM_X4(af[0], af[1], af[2], af[3], sQ + qOff + kk * 2);
            #pragma unroll
            for (int pr = 0; pr < 4; pr++)
                LDSM_X4(bfr[2*pr][0], bfr[2*pr][1], bfr[2*pr+1][0], bfr[2*pr+1][1],
                        sK + kOff + kk * 2 + pr * 16 * (AT_LDK * 2));
            #pragma unroll
            for (int nj = 0; nj < 8; nj++)
                mma16816(s[nj], af, bfr[nj]);
        }

        // ---- online softmax ----
        const float simv = sims[b * M_DOCS + (kt >> 4)] * beta;
        float lg[8][4];
        float mt0 = -3.0e38f, mt1 = -3.0e38f;
        #pragma unroll
        for (int nj = 0; nj < 8; nj++) {
            lg[nj][0] = s[nj][0] * 0.03125f + simv;
            lg[nj][1] = s[nj][1] * 0.03125f + simv;
            lg[nj][2] = s[nj][2] * 0.03125f + simv;
            lg[nj][3] = s[nj][3] * 0.03125f + simv;
            mt0 = fmaxf(mt0, fmaxf(lg[nj][0], lg[nj][1]));
            mt1 = fmaxf(mt1, fmaxf(lg[nj][2], lg[nj][3]));
        }
        mt0 = fmaxf(mt0, __shfl_xor_sync(0xffffffffu, mt0, 1, 4));
        mt0 = fmaxf(mt0, __shfl_xor_sync(0xffffffffu, mt0, 2, 4));
        mt1 = fmaxf(mt1, __shfl_xor_sync(0xffffffffu, mt1, 1, 4));
        mt1 = fmaxf(mt1, __shfl_xor_sync(0xffffffffu, mt1, 2, 4));
        float mn0 = fmaxf(m0r, mt0), mn1 = fmaxf(m1r, mt1);
        float c0 = __expf(m0r - mn0), c1 = __expf(m1r - mn1);
        m0r = mn0; m1r = mn1; l0r *= c0; l1r *= c1;
        #pragma unroll
        for (int nj = 0; nj < 16; nj++) {
            o[nj][0] *= c0; o[nj][1] *= c0;
            o[nj][2] *= c1; o[nj][3] *= c1;
        }

        uint32_t ph01[8], ph23[8], pl01[8], pl23[8];
        #pragma unroll
        for (int nj = 0; nj < 8; nj++) {
            float p0 = __expf(lg[nj][0] - mn0), p1 = __expf(lg[nj][1] - mn0);
            float p2 = __expf(lg[nj][2] - mn1), p3 = __expf(lg[nj][3] - mn1);
            l0r += p0 + p1; l1r += p2 + p3;
            __nv_bfloat162 h01 = __float22bfloat162_rn(make_float2(p0, p1));
            __nv_bfloat162 h23 = __float22bfloat162_rn(make_float2(p2, p3));
            float2 b01 = __bfloat1622float2(h01);
            float2 b23 = __bfloat1622float2(h23);
            ph01[nj] = *(uint32_t*)&h01;
            ph23[nj] = *(uint32_t*)&h23;
            pl01[nj] = pack_bf16(p0 - b01.x, p1 - b01.y);
            pl23[nj] = pack_bf16(p2 - b23.x, p3 - b23.y);
        }

        // ---- O += ph*Vh + ph*Vl + pl*Vh ----
        #pragma unroll
        for (int kbi = 0; kbi < 4; kbi++) {
            uint32_t ah[4] = { ph01[2*kbi], ph23[2*kbi], ph01[2*kbi+1], ph23[2*kbi+1] };
            uint32_t al[4] = { pl01[2*kbi], pl23[2*kbi], pl01[2*kbi+1], pl23[2*kbi+1] };
            #pragma unroll
            for (int pr = 0; pr < 8; pr++) {
                uint32_t bh2[2], bh2b[2], bl2[2], bl2b[2];
                LDSM_X4(bh2[0], bh2[1], bh2b[0], bh2b[1],
                        sVh + vOff + kbi * 32 + pr * 16 * (AT_LDV * 2));
                LDSM_X4(bl2[0], bl2[1], bl2b[0], bl2b[1],
                        sVl + vOff + kbi * 32 + pr * 16 * (AT_LDV * 2));
                mma16816(o[2*pr],     ah, bh2);
                mma16816(o[2*pr],     ah, bl2);
                mma16816(o[2*pr],     al, bh2);
                mma16816(o[2*pr + 1], ah, bh2b);
                mma16816(o[2*pr + 1], ah, bl2b);
                mma16816(o[2*pr + 1], al, bh2b);
            }
        }
        __syncthreads();   // compute done before next iter overwrites this stage
    }

    // epilogue: reduce l across quad, normalize, write split bf16
    l0r += __shfl_xor_sync(0xffffffffu, l0r, 1, 4);
    l0r += __shfl_xor_sync(0xffffffffu, l0r, 2, 4);
    l1r += __shfl_xor_sync(0xffffffffu, l1r, 1, 4);
    l1r += __shfl_xor_sync(0xffffffffu, l1r, 2, 4);
    float inv0 = 1.0f / l0r, inv1 = 1.0f / l1r;

    int row0 = qrow0 + wid * 16 + g;
    #pragma unroll
    for (int nj = 0; nj < 16; nj++) {
        int col = nj * 8 + 2 * t4;
        #pragma unroll
        for (int half = 0; half < 2; half++) {
            float v0 = o[nj][half * 2 + 0] * (half ? inv1 : inv0);
            float v1 = o[nj][half * 2 + 1] * (half ? inv1 : inv0);
            size_t off = (size_t)(row0 + half * 8) * DIM_ + h * HD_ + col;
            __nv_bfloat162 hi2;
            hi2.x = __float2bfloat16(v0);
            hi2.y = __float2bfloat16(v1);
            *(uint32_t*)(Oh + off) = *(uint32_t*)&hi2;
            *(uint32_t*)(Ol + off) =
                pack_bf16(v0 - __bfloat162float(hi2.x),
                          v1 - __bfloat162float(hi2.y));
        }
    }
}

// ---------------------------------------------------------------------------
extern "C" void kernel_launch(void* const* d_in, const int* in_sizes, int n_in,
                              void* d_out, int out_size)
{
    const float* x    = (const float*)d_in[0];
    const float* ctx  = (const float*)d_in[1];
    const float* sims = (const float*)d_in[2];
    const float* Wq   = (const float*)d_in[3];
    const float* Wkv  = (const float*)d_in[4];
    const float* beta = (const float*)d_in[5];
    const float* Wout = (const float*)d_in[6];
    const float* bout = (const float*)d_in[7];
    float* out = (float*)d_out;

    __nv_bfloat16 *xh, *xl, *ch, *cl, *oh, *ol;
    __nv_bfloat16 *wqh, *wql, *wkvh, *wkvl, *woh, *wol;
    __nv_bfloat16 *qb, *kbp, *vth, *vtl;
    cudaGetSymbolAddress((void**)&xh,  g_xh);
    cudaGetSymbolAddress((void**)&xl,  g_xl);
    cudaGetSymbolAddress((void**)&ch,  g_ch);
    cudaGetSymbolAddress((void**)&cl,  g_cl);
    cudaGetSymbolAddress((void**)&oh,  g_oh);
    cudaGetSymbolAddress((void**)&ol,  g_ol);
    cudaGetSymbolAddress((void**)&wqh, g_wqh);
    cudaGetSymbolAddress((void**)&wql, g_wql);
    cudaGetSymbolAddress((void**)&wkvh, g_wkvh);
    cudaGetSymbolAddress((void**)&wkvl, g_wkvl);
    cudaGetSymbolAddress((void**)&woh, g_woh);
    cudaGetSymbolAddress((void**)&wol, g_wol);
    cudaGetSymbolAddress((void**)&qb,  g_qb);
    cudaGetSymbolAddress((void**)&kbp, g_kb);
    cudaGetSymbolAddress((void**)&vth, g_vth);
    cudaGetSymbolAddress((void**)&vtl, g_vtl);

    cudaFuncSetAttribute(gemm_mma, cudaFuncAttributeMaxDynamicSharedMemorySize,
                         GM_SMEM_DYN);
    cudaFuncSetAttribute(ca_attn_mma, cudaFuncAttributeMaxDynamicSharedMemorySize,
                         AT_SMEM);

    // --- input conversions ---
    {
        int t1 = B_ * N_ * DIM_;
        conv_split<<<(t1 + 255) / 256, 256>>>(x, xh, xl, t1);
        int t2 = B_ * L_ * DIM_;
        conv_split<<<(t2 + 255) / 256, 256>>>(ctx, ch, cl, t2);
        conv_w_t<<<dim3(DIM_ / 32, DIM_ / 32), dim3(32, 8)>>>(Wq, wqh, wql,
                                                              DIM_, DIM_);
        conv_w_t<<<dim3((2 * DIM_) / 32, DIM_ / 32), dim3(32, 8)>>>(
            Wkv, wkvh, wkvl, DIM_, 2 * DIM_);
        conv_w_t<<<dim3(DIM_ / 32, DIM_ / 32), dim3(32, 8)>>>(Wout, woh, wol,
                                                              DIM_, DIM_);
    }

    // Q = x @ Wq  -> qb (plain bf16, fused)
    gemm_mma<<<dim3(DIM_ / GM_BN, (B_ * N_) / GM_BM), 256, GM_SMEM_DYN>>>(
        xh, xl, wqh, wql, nullptr, nullptr, qb, nullptr, nullptr,
        B_ * N_, DIM_, DIM_, 1);

    // KV = ctx @ Wkv -> kb (plain) + vth/vtl (split transposed), fused
    gemm_mma<<<dim3((2 * DIM_) / GM_BN, (B_ * L_) / GM_BM), 256, GM_SMEM_DYN>>>(
        ch, cl, wkvh, wkvl, nullptr, nullptr, kbp, vth, vtl,
        B_ * L_, 2 * DIM_, DIM_, 2);

    // attention -> oh/ol (split bf16, fused)
    ca_attn_mma<<<dim3(N_ / 128, HEADS_, B_), 256, AT_SMEM>>>(
        qb, kbp, vth, vtl, sims, beta, oh, ol);

    // out = O @ Wout + bout (fp32)
    gemm_mma<<<dim3(DIM_ / GM_BN, (B_ * N_) / GM_BM), 256, GM_SMEM_DYN>>>(
        oh, ol, woh, wol, bout, out, nullptr, nullptr, nullptr,
        B_ * N_, DIM_, DIM_, 0);
}

// round 12
// speedup vs baseline: 1.5028x; 1.5028x over previous
#include <cuda_runtime.h>
#include <cuda_bf16.h>
#include <math.h>
#include <stdint.h>

// Problem constants
#define B_     2
#define N_     1024
#define DIM_   1024
#define HEADS_ 8
#define HD_    128
#define L_     4096   // m * nc
#define M_DOCS 4

// ---------------------------------------------------------------------------
// Scratch (__device__ globals; allocation-free rule)
// ---------------------------------------------------------------------------
// split-bf16 operand buffers for GEMM inputs
__device__ __nv_bfloat16 g_xh [(B_*N_) * DIM_];
__device__ __nv_bfloat16 g_xl [(B_*N_) * DIM_];
__device__ __nv_bfloat16 g_ch [(B_*L_) * DIM_];
__device__ __nv_bfloat16 g_cl [(B_*L_) * DIM_];
__device__ __nv_bfloat16 g_oh [(B_*N_) * DIM_];   // attn output, split hi
__device__ __nv_bfloat16 g_ol [(B_*N_) * DIM_];   // attn output, split lo
// weights transposed to [N,K]
__device__ __nv_bfloat16 g_wqh [DIM_ * DIM_];
__device__ __nv_bfloat16 g_wql [DIM_ * DIM_];
__device__ __nv_bfloat16 g_wkvh[(2*DIM_) * DIM_];
__device__ __nv_bfloat16 g_wkvl[(2*DIM_) * DIM_];
__device__ __nv_bfloat16 g_woh [DIM_ * DIM_];
__device__ __nv_bfloat16 g_wol [DIM_ * DIM_];

// attention operands
__device__ __nv_bfloat16 g_qb [(B_*N_) * DIM_];           // Q plain bf16
__device__ __nv_bfloat16 g_kb [(B_*L_) * DIM_];           // K plain bf16
__device__ __nv_bfloat16 g_vrh[(B_*L_) * DIM_];           // V row-major hi
__device__ __nv_bfloat16 g_vrl[(B_*L_) * DIM_];           // V row-major lo
__device__ __nv_bfloat16 g_vth[B_*HEADS_*HD_ * L_];       // V^T hi [b*1024+d][key]
__device__ __nv_bfloat16 g_vtl[B_*HEADS_*HD_ * L_];       // V^T lo

// ---------------------------------------------------------------------------
// PTX helpers — ONLY non-'a' features (compute_103 PTX: no tcgen05).
// ---------------------------------------------------------------------------
#define CP_ASYNC16(dst, src) \
    asm volatile("cp.async.cg.shared.global [%0], [%1], 16;\n" \
                 :: "r"(dst), "l"(src) : "memory")
#define CP_ASYNC_COMMIT()  asm volatile("cp.async.commit_group;\n" ::: "memory")
#define CP_ASYNC_WAIT1()   asm volatile("cp.async.wait_group 1;\n" ::: "memory")
#define CP_ASYNC_WAIT0()   asm volatile("cp.async.wait_group 0;\n" ::: "memory")

#define LDSM_X4(r0, r1, r2, r3, a) \
    asm volatile("ldmatrix.sync.aligned.m8n8.x4.shared.b16 {%0,%1,%2,%3}, [%4];" \
                 : "=r"(r0), "=r"(r1), "=r"(r2), "=r"(r3) : "r"(a))

__device__ __forceinline__ uint32_t smem_u32(const void* p) {
    uint32_t a;
    asm("{ .reg .u64 t; cvta.to.shared.u64 t, %1; cvt.u32.u64 %0, t; }"
        : "=r"(a) : "l"(p));
    return a;
}

// D += A @ B^T : m16n8k16, bf16 in, fp32 accum (layout validated R8/R10)
__device__ __forceinline__ void mma16816(float* d, const uint32_t* a,
                                         const uint32_t* b) {
    asm volatile(
        "mma.sync.aligned.m16n8k16.row.col.f32.bf16.bf16.f32 "
        "{%0,%1,%2,%3}, {%4,%5,%6,%7}, {%8,%9}, {%0,%1,%2,%3};"
        : "+f"(d[0]), "+f"(d[1]), "+f"(d[2]), "+f"(d[3])
        : "r"(a[0]), "r"(a[1]), "r"(a[2]), "r"(a[3]), "r"(b[0]), "r"(b[1]));
}

__device__ __forceinline__ uint32_t pack_bf16(float a, float b) {
    __nv_bfloat162 t = __float22bfloat162_rn(make_float2(a, b));
    return *(uint32_t*)&t;
}

// ---------------------------------------------------------------------------
// Conversion kernels
// ---------------------------------------------------------------------------
__global__ void conv_split(const float* __restrict__ A,
                           __nv_bfloat16* __restrict__ Ah,
                           __nv_bfloat16* __restrict__ Al, int total)
{
    int i = blockIdx.x * blockDim.x + threadIdx.x;
    if (i >= total) return;
    float v = A[i];
    __nv_bfloat16 hi = __float2bfloat16(v);
    Ah[i] = hi;
    Al[i] = __float2bfloat16(v - __bfloat162float(hi));
}

// W[K,N] fp32 -> Wh/Wl [N,K] bf16 (transpose + split)
__global__ void conv_w_t(const float* __restrict__ W,
                         __nv_bfloat16* __restrict__ Wh,
                         __nv_bfloat16* __restrict__ Wl, int K, int N)
{
    __shared__ float t[32][33];
    int k0 = blockIdx.y * 32, n0 = blockIdx.x * 32;
    int tx = threadIdx.x, ty = threadIdx.y;
    #pragma unroll
    for (int i = 0; i < 32; i += 8)
        t[ty + i][tx] = W[(size_t)(k0 + ty + i) * N + n0 + tx];
    __syncthreads();
    #pragma unroll
    for (int i = 0; i < 32; i += 8) {
        float v = t[tx][ty + i];
        __nv_bfloat16 hi = __float2bfloat16(v);
        size_t o = (size_t)(n0 + ty + i) * K + k0 + tx;
        Wh[o] = hi;
        Wl[o] = __float2bfloat16(v - __bfloat162float(hi));
    }
}

// V row-major [b*L][1024] bf16 -> V^T [b*1024+d][key] (coalesced both sides)
__global__ void vt_trans(const __nv_bfloat16* __restrict__ Vr,
                         __nv_bfloat16* __restrict__ Vt)
{
    __shared__ __nv_bfloat16 t[32][33];
    int key0 = blockIdx.x * 32, d0 = blockIdx.y * 32;
    int b = blockIdx.z;
    int tx = threadIdx.x, ty = threadIdx.y;   // 32 x 8
    #pragma unroll
    for (int i = 0; i < 32; i += 8)
        t[ty + i][tx] = Vr[(size_t)(b * L_ + key0 + ty + i) * DIM_ + d0 + tx];
    __syncthreads();
    #pragma unroll
    for (int i = 0; i < 32; i += 8) {
        int d = d0 + ty + i;
        Vt[((size_t)(b * DIM_ + d)) * L_ + key0 + tx] = t[tx][ty + i];
    }
}

// ---------------------------------------------------------------------------
// mma.sync split-bf16 GEMM with ldmatrix + fused epilogues.
//   mode 0: C fp32 = acc + bias
//   mode 1: Cb bf16 plain (Q path)
//   mode 2: KV path — col<1024: kb plain bf16; col>=1024: V split ROW-MAJOR
//           (coalesced; transpose happens in vt_trans afterwards)
// ---------------------------------------------------------------------------
#define GM_BM  128
#define GM_BN  128
#define GM_BK  64
#define GM_LDA 72
#define GM_STAGE_ELEMS ((GM_BM + GM_BN) * GM_LDA)
#define GM_SMEM_DYN (2 * GM_STAGE_ELEMS * 2)

__global__ __launch_bounds__(256, 2)
void gemm_mma(const __nv_bfloat16* __restrict__ Ah,
              const __nv_bfloat16* __restrict__ Al,
              const __nv_bfloat16* __restrict__ Bh,
              const __nv_bfloat16* __restrict__ Bl,
              const float* __restrict__ bias, float* __restrict__ C,
              __nv_bfloat16* __restrict__ Cb,
              __nv_bfloat16* __restrict__ vrh,
              __nv_bfloat16* __restrict__ vrl,
              int M, int N, int K, int mode)
{
    extern __shared__ __align__(16) __nv_bfloat16 dsm[];

    const int tid   = threadIdx.x;
    const int wid   = tid >> 5;
    const int lane  = tid & 31;
    const int g     = lane >> 2;
    const int t4    = lane & 3;
    const int warpM = wid & 3;
    const int warpN = wid >> 2;
    const int m0 = blockIdx.y * GM_BM;
    const int n0 = blockIdx.x * GM_BN;
    const int KB = K * 2;
    const int kchunks = K / GM_BK;
    const int NCHUNK = 3 * kchunks;

    const uint32_t smem_base = smem_u32(dsm);

    // ldmatrix lane offsets (bytes, relative to tile base)
    const uint32_t aOff = (uint32_t)(warpM * 32 + (lane & 15)) * (GM_LDA * 2)
                        + ((lane >> 4) << 3) * 2;
    const uint32_t bOff = (uint32_t)(warpN * 64 + ((lane & 16) >> 1) + (lane & 7))
                        * (GM_LDA * 2) + ((lane & 8) ? 16 : 0);

    float acc[2][8][4];
    #pragma unroll
    for (int mi = 0; mi < 2; mi++)
        #pragma unroll
        for (int ni = 0; ni < 8; ni++)
            #pragma unroll
            for (int r = 0; r < 4; r++) acc[mi][ni][r] = 0.f;

    auto load_tile = [&](int s, int c) {
        int pass = c / kchunks;
        int kc   = c - pass * kchunks;
        const char* Asrc = (const char*)((pass < 2) ? Ah : Al)
                         + (size_t)m0 * KB + (size_t)kc * (GM_BK * 2);
        const char* Bsrc = (const char*)((pass == 1) ? Bl : Bh)
                         + (size_t)n0 * KB + (size_t)kc * (GM_BK * 2);
        uint32_t As = smem_base + s * (GM_STAGE_ELEMS * 2);
        uint32_t Bs = As + GM_BM * GM_LDA * 2;
        #pragma unroll
        for (int i = 0; i < 8; i++) {
            int u = tid + i * 256;
            if (i < 4) {
                int row = u >> 3, ch = u & 7;
                CP_ASYNC16(As + row * (GM_LDA * 2) + ch * 16,
                           Asrc + (size_t)row * KB + ch * 16);
            } else {
                int v = u - 1024;
                int row = v >> 3, ch = v & 7;
                CP_ASYNC16(Bs + row * (GM_LDA * 2) + ch * 16,
                           Bsrc + (size_t)row * KB + ch * 16);
            }
        }
        CP_ASYNC_COMMIT();
    };

    load_tile(0, 0);

    for (int c = 0; c < NCHUNK; c++) {
        if (c + 1 < NCHUNK) {
            load_tile((c + 1) & 1, c + 1);
            CP_ASYNC_WAIT1();
        } else {
            CP_ASYNC_WAIT0();
        }
        __syncthreads();

        uint32_t As = smem_base + (c & 1) * (GM_STAGE_ELEMS * 2);
        uint32_t Bs = As + GM_BM * GM_LDA * 2;
        uint32_t aAddr = As + aOff;
        uint32_t bAddr = Bs + bOff;

        #pragma unroll
        for (int kk = 0; kk < GM_BK; kk += 16) {
            uint32_t af[2][4], bfr[8][2];
            #pragma unroll
            for (int mi = 0; mi < 2; mi++)
                LDSM_X4(af[mi][0], af[mi][1], af[mi][2], af[mi][3],
                        aAddr + kk * 2 + mi * 16 * (GM_LDA * 2));
            #pragma unroll
            for (int pr = 0; pr < 4; pr++)
                LDSM_X4(bfr[2*pr][0], bfr[2*pr][1], bfr[2*pr+1][0], bfr[2*pr+1][1],
                        bAddr + kk * 2 + pr * 16 * (GM_LDA * 2));
            #pragma unroll
            for (int mi = 0; mi < 2; mi++)
                #pragma unroll
                for (int ni = 0; ni < 8; ni++)
                    mma16816(acc[mi][ni], af[mi], bfr[ni]);
        }
        __syncthreads();
    }

    // fused epilogue (all branches COALESCED)
    #pragma unroll
    for (int mi = 0; mi < 2; mi++) {
        int rowA = m0 + warpM * 32 + mi * 16 + g;
        #pragma unroll
        for (int ni = 0; ni < 8; ni++) {
            int col = n0 + warpN * 64 + ni * 8 + 2 * t4;
            #pragma unroll
            for (int half = 0; half < 2; half++) {
                int row = rowA + half * 8;
                float v0 = acc[mi][ni][half * 2 + 0];
                float v1 = acc[mi][ni][half * 2 + 1];
                if (mode == 0) {
                    *(float2*)(C + (size_t)row * N + col) =
                        make_float2(v0 + bias[col], v1 + bias[col + 1]);
                } else if (mode == 1) {
                    *(uint32_t*)(Cb + (size_t)row * N + col) = pack_bf16(v0, v1);
                } else {
                    if (col < 1024) {
                        *(uint32_t*)(Cb + (size_t)row * 1024 + col) =
                            pack_bf16(v0, v1);
                    } else {
                        int c2 = col - 1024;
                        size_t off = (size_t)row * 1024 + c2;
                        __nv_bfloat16 h0 = __float2bfloat16(v0);
                        __nv_bfloat16 h1 = __float2bfloat16(v1);
                        __nv_bfloat162 hp; hp.x = h0; hp.y = h1;
                        *(uint32_t*)(vrh + off) = *(uint32_t*)&hp;
                        *(uint32_t*)(vrl + off) =
                            pack_bf16(v0 - __bfloat162float(h0),
                                      v1 - __bfloat162float(h1));
                    }
                }
            }
        }
    }
}

// ---------------------------------------------------------------------------
// Flash attention on mma.sync, ldmatrix fragments, double-buffered K/V.
// (unchanged from R11 — numerics validated, rel_err 1.37e-4)
// ---------------------------------------------------------------------------
#define AT_LDQ 136
#define AT_LDK 136
#define AT_LDV 72
#define AT_ST_ELEMS (64*AT_LDK + 2*128*AT_LDV)
#define AT_SMEM ((128*AT_LDQ + 2*AT_ST_ELEMS) * 2)   // 143360 B

__global__ __launch_bounds__(256, 1)
void ca_attn_mma(const __nv_bfloat16* __restrict__ qb,
                 const __nv_bfloat16* __restrict__ kb,
                 const __nv_bfloat16* __restrict__ vth,
                 const __nv_bfloat16* __restrict__ vtl,
                 const float* __restrict__ sims,
                 const float* __restrict__ beta_p,
                 __nv_bfloat16* __restrict__ Oh,
                 __nv_bfloat16* __restrict__ Ol)
{
    extern __shared__ __align__(16) __nv_bfloat16 smattn[];
    const uint32_t sQ = smem_u32(smattn);

    const int qt = blockIdx.x, h = blockIdx.y, b = blockIdx.z;
    const int tid = threadIdx.x, wid = tid >> 5, lane = tid & 31;
    const int g = lane >> 2, t4 = lane & 3;
    const float beta = beta_p[0];
    const int qrow0 = b * N_ + qt * 128;
    const size_t vbase = (size_t)(b * HEADS_ + h) * HD_ * (size_t)L_;

    const uint32_t qOff = (uint32_t)(wid * 16 + (lane & 15)) * (AT_LDQ * 2)
                        + ((lane >> 4) << 3) * 2;
    const uint32_t kOff = (uint32_t)(((lane & 16) >> 1) + (lane & 7)) * (AT_LDK * 2)
                        + ((lane & 8) ? 16 : 0);
    const uint32_t vOff = (uint32_t)(((lane & 16) >> 1) + (lane & 7)) * (AT_LDV * 2)
                        + ((lane & 8) ? 16 : 0);

    #pragma unroll
    for (int i = 0; i < 8; i++) {
        int u = tid + i * 256, r = u >> 4, ch = u & 15;
        CP_ASYNC16(sQ + r * (AT_LDQ * 2) + ch * 16,
                   (const char*)qb + ((size_t)(qrow0 + r) * DIM_ + h * HD_) * 2 + ch * 16);
    }
    CP_ASYNC_COMMIT();

    auto stage_base = [&](int s) -> uint32_t {
        return sQ + 128 * AT_LDQ * 2 + s * (AT_ST_ELEMS * 2);
    };
    auto load_kv = [&](int s, int kt) {
        uint32_t sK  = stage_base(s);
        uint32_t sVh = sK + 64 * AT_LDK * 2;
        uint32_t sVl = sVh + 128 * AT_LDV * 2;
        const size_t krow0 = (size_t)(b * L_ + kt * 64);
        #pragma unroll
        for (int i = 0; i < 4; i++) {
            int u = tid + i * 256, r = u >> 4, ch = u & 15;
            CP_ASYNC16(sK + r * (AT_LDK * 2) + ch * 16,
                       (const char*)kb + ((krow0 + r) * DIM_ + h * HD_) * 2 + ch * 16);
        }
        #pragma unroll
        for (int i = 0; i < 4; i++) {
            int u = tid + i * 256, r = u >> 3, ch = u & 7;
            size_t src = (vbase + (size_t)r * L_ + kt * 64) * 2 + ch * 16;
            CP_ASYNC16(sVh + r * (AT_LDV * 2) + ch * 16, (const char*)vth + src);
        }
        #pragma unroll
        for (int i = 0; i < 4; i++) {
            int u = tid + i * 256, r = u >> 3, ch = u & 7;
            size_t src = (vbase + (size_t)r * L_ + kt * 64) * 2 + ch * 16;
            CP_ASYNC16(sVl + r * (AT_LDV * 2) + ch * 16, (const char*)vtl + src);
        }
        CP_ASYNC_COMMIT();
    };

    load_kv(0, 0);

    float o[16][4];
    #pragma unroll
    for (int nj = 0; nj < 16; nj++)
        #pragma unroll
        for (int r = 0; r < 4; r++) o[nj][r] = 0.f;
    float m0r = -3.0e38f, m1r = -3.0e38f, l0r = 0.f, l1r = 0.f;

    for (int kt = 0; kt < 64; kt++) {
        if (kt + 1 < 64) {
            load_kv((kt + 1) & 1, kt + 1);
            CP_ASYNC_WAIT1();
        } else {
            CP_ASYNC_WAIT0();
        }
        __syncthreads();

        uint32_t sK  = stage_base(kt & 1);
        uint32_t sVh = sK + 64 * AT_LDK * 2;
        uint32_t sVl = sVh + 128 * AT_LDV * 2;

        float s[8][4];
        #pragma unroll
        for (int nj = 0; nj < 8; nj++)
            #pragma unroll
            for (int r = 0; r < 4; r++) s[nj][r] = 0.f;

        #pragma unroll
        for (int kk = 0; kk < 128; kk += 16) {
            uint32_t af[4], bfr[8][2];
            LDSM_X4(af[0], af[1], af[2], af[3], sQ + qOff + kk * 2);
            #pragma unroll
            for (int pr = 0; pr < 4; pr++)
                LDSM_X4(bfr[2*pr][0], bfr[2*pr][1], bfr[2*pr+1][0], bfr[2*pr+1][1],
                        sK + kOff + kk * 2 + pr * 16 * (AT_LDK * 2));
            #pragma unroll
            for (int nj = 0; nj < 8; nj++)
                mma16816(s[nj], af, bfr[nj]);
        }

        const float simv = sims[b * M_DOCS + (kt >> 4)] * beta;
        float lg[8][4];
        float mt0 = -3.0e38f, mt1 = -3.0e38f;
        #pragma unroll
        for (int nj = 0; nj < 8; nj++) {
            lg[nj][0] = s[nj][0] * 0.03125f + simv;
            lg[nj][1] = s[nj][1] * 0.03125f + simv;
            lg[nj][2] = s[nj][2] * 0.03125f + simv;
            lg[nj][3] = s[nj][3] * 0.03125f + simv;
            mt0 = fmaxf(mt0, fmaxf(lg[nj][0], lg[nj][1]));
            mt1 = fmaxf(mt1, fmaxf(lg[nj][2], lg[nj][3]));
        }
        mt0 = fmaxf(mt0, __shfl_xor_sync(0xffffffffu, mt0, 1, 4));
        mt0 = fmaxf(mt0, __shfl_xor_sync(0xffffffffu, mt0, 2, 4));
        mt1 = fmaxf(mt1, __shfl_xor_sync(0xffffffffu, mt1, 1, 4));
        mt1 = fmaxf(mt1, __shfl_xor_sync(0xffffffffu, mt1, 2, 4));
        float mn0 = fmaxf(m0r, mt0), mn1 = fmaxf(m1r, mt1);
        float c0 = __expf(m0r - mn0), c1 = __expf(m1r - mn1);
        m0r = mn0; m1r = mn1; l0r *= c0; l1r *= c1;
        #pragma unroll
        for (int nj = 0; nj < 16; nj++) {
            o[nj][0] *= c0; o[nj][1] *= c0;
            o[nj][2] *= c1; o[nj][3] *= c1;
        }

        uint32_t ph01[8], ph23[8], pl01[8], pl23[8];
        #pragma unroll
        for (int nj = 0; nj < 8; nj++) {
            float p0 = __expf(lg[nj][0] - mn0), p1 = __expf(lg[nj][1] - mn0);
            float p2 = __expf(lg[nj][2] - mn1), p3 = __expf(lg[nj][3] - mn1);
            l0r += p0 + p1; l1r += p2 + p3;
            __nv_bfloat162 h01 = __float22bfloat162_rn(make_float2(p0, p1));
            __nv_bfloat162 h23 = __float22bfloat162_rn(make_float2(p2, p3));
            float2 b01 = __bfloat1622float2(h01);
            float2 b23 = __bfloat1622float2(h23);
            ph01[nj] = *(uint32_t*)&h01;
            ph23[nj] = *(uint32_t*)&h23;
            pl01[nj] = pack_bf16(p0 - b01.x, p1 - b01.y);
            pl23[nj] = pack_bf16(p2 - b23.x, p3 - b23.y);
        }

        #pragma unroll
        for (int kbi = 0; kbi < 4; kbi++) {
            uint32_t ah[4] = { ph01[2*kbi], ph23[2*kbi], ph01[2*kbi+1], ph23[2*kbi+1] };
            uint32_t al[4] = { pl01[2*kbi], pl23[2*kbi], pl01[2*kbi+1], pl23[2*kbi+1] };
            #pragma unroll
            for (int pr = 0; pr < 8; pr++) {
                uint32_t bh2[2], bh2b[2], bl2[2], bl2b[2];
                LDSM_X4(bh2[0], bh2[1], bh2b[0], bh2b[1],
                        sVh + vOff + kbi * 32 + pr * 16 * (AT_LDV * 2));
                LDSM_X4(bl2[0], bl2[1], bl2b[0], bl2b[1],
                        sVl + vOff + kbi * 32 + pr * 16 * (AT_LDV * 2));
                mma16816(o[2*pr],     ah, bh2);
                mma16816(o[2*pr],     ah, bl2);
                mma16816(o[2*pr],     al, bh2);
                mma16816(o[2*pr + 1], ah, bh2b);
                mma16816(o[2*pr + 1], ah, bl2b);
                mma16816(o[2*pr + 1], al, bh2b);
            }
        }
        __syncthreads();
    }

    l0r += __shfl_xor_sync(0xffffffffu, l0r, 1, 4);
    l0r += __shfl_xor_sync(0xffffffffu, l0r, 2, 4);
    l1r += __shfl_xor_sync(0xffffffffu, l1r, 1, 4);
    l1r += __shfl_xor_sync(0xffffffffu, l1r, 2, 4);
    float inv0 = 1.0f / l0r, inv1 = 1.0f / l1r;

    int row0 = qrow0 + wid * 16 + g;
    #pragma unroll
    for (int nj = 0; nj < 16; nj++) {
        int col = nj * 8 + 2 * t4;
        #pragma unroll
        for (int half = 0; half < 2; half++) {
            float v0 = o[nj][half * 2 + 0] * (half ? inv1 : inv0);
            float v1 = o[nj][half * 2 + 1] * (half ? inv1 : inv0);
            size_t off = (size_t)(row0 + half * 8) * DIM_ + h * HD_ + col;
            __nv_bfloat162 hi2;
            hi2.x = __float2bfloat16(v0);
            hi2.y = __float2bfloat16(v1);
            *(uint32_t*)(Oh + off) = *(uint32_t*)&hi2;
            *(uint32_t*)(Ol + off) =
                pack_bf16(v0 - __bfloat162float(hi2.x),
                          v1 - __bfloat162float(hi2.y));
        }
    }
}

// ---------------------------------------------------------------------------
extern "C" void kernel_launch(void* const* d_in, const int* in_sizes, int n_in,
                              void* d_out, int out_size)
{
    const float* x    = (const float*)d_in[0];
    const float* ctx  = (const float*)d_in[1];
    const float* sims = (const float*)d_in[2];
    const float* Wq   = (const float*)d_in[3];
    const float* Wkv  = (const float*)d_in[4];
    const float* beta = (const float*)d_in[5];
    const float* Wout = (const float*)d_in[6];
    const float* bout = (const float*)d_in[7];
    float* out = (float*)d_out;

    __nv_bfloat16 *xh, *xl, *ch, *cl, *oh, *ol;
    __nv_bfloat16 *wqh, *wql, *wkvh, *wkvl, *woh, *wol;
    __nv_bfloat16 *qb, *kbp, *vrh, *vrl, *vth, *vtl;
    cudaGetSymbolAddress((void**)&xh,  g_xh);
    cudaGetSymbolAddress((void**)&xl,  g_xl);
    cudaGetSymbolAddress((void**)&ch,  g_ch);
    cudaGetSymbolAddress((void**)&cl,  g_cl);
    cudaGetSymbolAddress((void**)&oh,  g_oh);
    cudaGetSymbolAddress((void**)&ol,  g_ol);
    cudaGetSymbolAddress((void**)&wqh, g_wqh);
    cudaGetSymbolAddress((void**)&wql, g_wql);
    cudaGetSymbolAddress((void**)&wkvh, g_wkvh);
    cudaGetSymbolAddress((void**)&wkvl, g_wkvl);
    cudaGetSymbolAddress((void**)&woh, g_woh);
    cudaGetSymbolAddress((void**)&wol, g_wol);
    cudaGetSymbolAddress((void**)&qb,  g_qb);
    cudaGetSymbolAddress((void**)&kbp, g_kb);
    cudaGetSymbolAddress((void**)&vrh, g_vrh);
    cudaGetSymbolAddress((void**)&vrl, g_vrl);
    cudaGetSymbolAddress((void**)&vth, g_vth);
    cudaGetSymbolAddress((void**)&vtl, g_vtl);

    cudaFuncSetAttribute(gemm_mma, cudaFuncAttributeMaxDynamicSharedMemorySize,
                         GM_SMEM_DYN);
    cudaFuncSetAttribute(ca_attn_mma, cudaFuncAttributeMaxDynamicSharedMemorySize,
                         AT_SMEM);

    // --- input conversions ---
    {
        int t1 = B_ * N_ * DIM_;
        conv_split<<<(t1 + 255) / 256, 256>>>(x, xh, xl, t1);
        int t2 = B_ * L_ * DIM_;
        conv_split<<<(t2 + 255) / 256, 256>>>(ctx, ch, cl, t2);
        conv_w_t<<<dim3(DIM_ / 32, DIM_ / 32), dim3(32, 8)>>>(Wq, wqh, wql,
                                                              DIM_, DIM_);
        conv_w_t<<<dim3((2 * DIM_) / 32, DIM_ / 32), dim3(32, 8)>>>(
            Wkv, wkvh, wkvl, DIM_, 2 * DIM_);
        conv_w_t<<<dim3(DIM_ / 32, DIM_ / 32), dim3(32, 8)>>>(Wout, woh, wol,
                                                              DIM_, DIM_);
    }

    // Q = x @ Wq  -> qb (plain bf16, fused)
    gemm_mma<<<dim3(DIM_ / GM_BN, (B_ * N_) / GM_BM), 256, GM_SMEM_DYN>>>(
        xh, xl, wqh, wql, nullptr, nullptr, qb, nullptr, nullptr,
        B_ * N_, DIM_, DIM_, 1);

    // KV = ctx @ Wkv -> kb (plain) + vrh/vrl (split, ROW-MAJOR, coalesced)
    gemm_mma<<<dim3((2 * DIM_) / GM_BN, (B_ * L_) / GM_BM), 256, GM_SMEM_DYN>>>(
        ch, cl, wkvh, wkvl, nullptr, nullptr, kbp, vrh, vrl,
        B_ * L_, 2 * DIM_, DIM_, 2);

    // transpose V (coalesced both sides)
    vt_trans<<<dim3(L_ / 32, DIM_ / 32, B_), dim3(32, 8)>>>(vrh, vth);
    vt_trans<<<dim3(L_ / 32, DIM_ / 32, B_), dim3(32, 8)>>>(vrl, vtl);

    // attention -> oh/ol (split bf16, fused)
    ca_attn_mma<<<dim3(N_ / 128, HEADS_, B_), 256, AT_SMEM>>>(
        qb, kbp, vth, vtl, sims, beta, oh, ol);

    // out = O @ Wout + bout (fp32)
    gemm_mma<<<dim3(DIM_ / GM_BN, (B_ * N_) / GM_BM), 256, GM_SMEM_DYN>>>(
        oh, ol, woh, wol, bout, out, nullptr, nullptr, nullptr,
        B_ * N_, DIM_, DIM_, 0);
}

// round 13
// speedup vs baseline: 1.7620x; 1.1724x over previous
#include <cuda_runtime.h>
#include <cuda_bf16.h>
#include <math.h>
#include <stdint.h>

// Problem constants
#define B_     2
#define N_     1024
#define DIM_   1024
#define HEADS_ 8
#define HD_    128
#define L_     4096   // m * nc
#define M_DOCS 4

// ---------------------------------------------------------------------------
// Scratch (__device__ globals; allocation-free rule)
// ---------------------------------------------------------------------------
__device__ __nv_bfloat16 g_xh [(B_*N_) * DIM_];
__device__ __nv_bfloat16 g_xl [(B_*N_) * DIM_];
__device__ __nv_bfloat16 g_ch [(B_*L_) * DIM_];
__device__ __nv_bfloat16 g_cl [(B_*L_) * DIM_];
__device__ __nv_bfloat16 g_oh [(B_*N_) * DIM_];   // attn output, split hi
__device__ __nv_bfloat16 g_ol [(B_*N_) * DIM_];   // attn output, split lo
// weights transposed to [N,K]
__device__ __nv_bfloat16 g_wqh [DIM_ * DIM_];
__device__ __nv_bfloat16 g_wql [DIM_ * DIM_];
__device__ __nv_bfloat16 g_wkvh[(2*DIM_) * DIM_];
__device__ __nv_bfloat16 g_wkvl[(2*DIM_) * DIM_];
__device__ __nv_bfloat16 g_woh [DIM_ * DIM_];
__device__ __nv_bfloat16 g_wol [DIM_ * DIM_];

// attention operands
__device__ __nv_bfloat16 g_qb [(B_*N_) * DIM_];           // Q plain bf16
__device__ __nv_bfloat16 g_kb [(B_*L_) * DIM_];           // K plain bf16
__device__ __nv_bfloat16 g_vrh[(B_*L_) * DIM_];           // V row-major hi
__device__ __nv_bfloat16 g_vrl[(B_*L_) * DIM_];           // V row-major lo
__device__ __nv_bfloat16 g_vth[B_*HEADS_*HD_ * L_];       // V^T hi [b*1024+d][key]
__device__ __nv_bfloat16 g_vtl[B_*HEADS_*HD_ * L_];       // V^T lo

// ---------------------------------------------------------------------------
// PTX helpers — ONLY non-'a' features (compute_103 PTX: no tcgen05).
// ---------------------------------------------------------------------------
#define CP_ASYNC16(dst, src) \
    asm volatile("cp.async.cg.shared.global [%0], [%1], 16;\n" \
                 :: "r"(dst), "l"(src) : "memory")
#define CP_ASYNC_COMMIT()  asm volatile("cp.async.commit_group;\n" ::: "memory")
#define CP_ASYNC_WAIT1()   asm volatile("cp.async.wait_group 1;\n" ::: "memory")
#define CP_ASYNC_WAIT0()   asm volatile("cp.async.wait_group 0;\n" ::: "memory")

#define LDSM_X4(r0, r1, r2, r3, a) \
    asm volatile("ldmatrix.sync.aligned.m8n8.x4.shared.b16 {%0,%1,%2,%3}, [%4];" \
                 : "=r"(r0), "=r"(r1), "=r"(r2), "=r"(r3) : "r"(a))

__device__ __forceinline__ uint32_t smem_u32(const void* p) {
    uint32_t a;
    asm("{ .reg .u64 t; cvta.to.shared.u64 t, %1; cvt.u32.u64 %0, t; }"
        : "=r"(a) : "l"(p));
    return a;
}

// D += A @ B^T : m16n8k16, bf16 in, fp32 accum (layout validated R8/R10)
__device__ __forceinline__ void mma16816(float* d, const uint32_t* a,
                                         const uint32_t* b) {
    asm volatile(
        "mma.sync.aligned.m16n8k16.row.col.f32.bf16.bf16.f32 "
        "{%0,%1,%2,%3}, {%4,%5,%6,%7}, {%8,%9}, {%0,%1,%2,%3};"
        : "+f"(d[0]), "+f"(d[1]), "+f"(d[2]), "+f"(d[3])
        : "r"(a[0]), "r"(a[1]), "r"(a[2]), "r"(a[3]), "r"(b[0]), "r"(b[1]));
}

__device__ __forceinline__ uint32_t pack_bf16(float a, float b) {
    __nv_bfloat162 t = __float22bfloat162_rn(make_float2(a, b));
    return *(uint32_t*)&t;
}

// ---------------------------------------------------------------------------
// Conversion kernels
// ---------------------------------------------------------------------------
__global__ void conv_split(const float* __restrict__ A,
                           __nv_bfloat16* __restrict__ Ah,
                           __nv_bfloat16* __restrict__ Al, int total)
{
    int i = blockIdx.x * blockDim.x + threadIdx.x;
    if (i >= total) return;
    float v = A[i];
    __nv_bfloat16 hi = __float2bfloat16(v);
    Ah[i] = hi;
    Al[i] = __float2bfloat16(v - __bfloat162float(hi));
}

// W[K,N] fp32 -> Wh/Wl [N,K] bf16 (transpose + split)
__global__ void conv_w_t(const float* __restrict__ W,
                         __nv_bfloat16* __restrict__ Wh,
                         __nv_bfloat16* __restrict__ Wl, int K, int N)
{
    __shared__ float t[32][33];
    int k0 = blockIdx.y * 32, n0 = blockIdx.x * 32;
    int tx = threadIdx.x, ty = threadIdx.y;
    #pragma unroll
    for (int i = 0; i < 32; i += 8)
        t[ty + i][tx] = W[(size_t)(k0 + ty + i) * N + n0 + tx];
    __syncthreads();
    #pragma unroll
    for (int i = 0; i < 32; i += 8) {
        float v = t[tx][ty + i];
        __nv_bfloat16 hi = __float2bfloat16(v);
        size_t o = (size_t)(n0 + ty + i) * K + k0 + tx;
        Wh[o] = hi;
        Wl[o] = __float2bfloat16(v - __bfloat162float(hi));
    }
}

// V row-major -> V^T, BOTH hi and lo in one launch (coalesced both sides)
__global__ void vt_trans2(const __nv_bfloat16* __restrict__ Vrh,
                          const __nv_bfloat16* __restrict__ Vrl,
                          __nv_bfloat16* __restrict__ Vth,
                          __nv_bfloat16* __restrict__ Vtl)
{
    __shared__ __nv_bfloat16 th[32][33];
    __shared__ __nv_bfloat16 tl[32][33];
    int key0 = blockIdx.x * 32, d0 = blockIdx.y * 32;
    int b = blockIdx.z;
    int tx = threadIdx.x, ty = threadIdx.y;   // 32 x 8
    #pragma unroll
    for (int i = 0; i < 32; i += 8) {
        size_t src = (size_t)(b * L_ + key0 + ty + i) * DIM_ + d0 + tx;
        th[ty + i][tx] = Vrh[src];
        tl[ty + i][tx] = Vrl[src];
    }
    __syncthreads();
    #pragma unroll
    for (int i = 0; i < 32; i += 8) {
        int d = d0 + ty + i;
        size_t dst = ((size_t)(b * DIM_ + d)) * L_ + key0 + tx;
        Vth[dst] = th[tx][ty + i];
        Vtl[dst] = tl[tx][ty + i];
    }
}

// ---------------------------------------------------------------------------
// mma.sync split-bf16 GEMM with ldmatrix + fused epilogues.
//   npasses: 1 = plain bf16 (Ah*Bh only), 3 = split (Ah*Bh + Ah*Bl + Al*Bh)
//   mode 0: C fp32 = acc + bias
//   mode 1: Cb bf16 plain
//   mode 2: V split ROW-MAJOR to vrh/vrl (coalesced)
// ---------------------------------------------------------------------------
#define GM_BM  128
#define GM_BN  128
#define GM_BK  64
#define GM_LDA 72
#define GM_STAGE_ELEMS ((GM_BM + GM_BN) * GM_LDA)
#define GM_SMEM_DYN (2 * GM_STAGE_ELEMS * 2)

__global__ __launch_bounds__(256, 2)
void gemm_mma(const __nv_bfloat16* __restrict__ Ah,
              const __nv_bfloat16* __restrict__ Al,
              const __nv_bfloat16* __restrict__ Bh,
              const __nv_bfloat16* __restrict__ Bl,
              const float* __restrict__ bias, float* __restrict__ C,
              __nv_bfloat16* __restrict__ Cb,
              __nv_bfloat16* __restrict__ vrh,
              __nv_bfloat16* __restrict__ vrl,
              int M, int N, int K, int mode, int npasses)
{
    extern __shared__ __align__(16) __nv_bfloat16 dsm[];

    const int tid   = threadIdx.x;
    const int wid   = tid >> 5;
    const int lane  = tid & 31;
    const int g     = lane >> 2;
    const int t4    = lane & 3;
    const int warpM = wid & 3;
    const int warpN = wid >> 2;
    const int m0 = blockIdx.y * GM_BM;
    const int n0 = blockIdx.x * GM_BN;
    const int KB = K * 2;
    const int kchunks = K / GM_BK;
    const int NCHUNK = npasses * kchunks;

    const uint32_t smem_base = smem_u32(dsm);

    const uint32_t aOff = (uint32_t)(warpM * 32 + (lane & 15)) * (GM_LDA * 2)
                        + ((lane >> 4) << 3) * 2;
    const uint32_t bOff = (uint32_t)(warpN * 64 + ((lane & 16) >> 1) + (lane & 7))
                        * (GM_LDA * 2) + ((lane & 8) ? 16 : 0);

    float acc[2][8][4];
    #pragma unroll
    for (int mi = 0; mi < 2; mi++)
        #pragma unroll
        for (int ni = 0; ni < 8; ni++)
            #pragma unroll
            for (int r = 0; r < 4; r++) acc[mi][ni][r] = 0.f;

    auto load_tile = [&](int s, int c) {
        int pass = c / kchunks;
        int kc   = c - pass * kchunks;
        const char* Asrc = (const char*)((pass < 2) ? Ah : Al)
                         + (size_t)m0 * KB + (size_t)kc * (GM_BK * 2);
        const char* Bsrc = (const char*)((pass == 1) ? Bl : Bh)
                         + (size_t)n0 * KB + (size_t)kc * (GM_BK * 2);
        uint32_t As = smem_base + s * (GM_STAGE_ELEMS * 2);
        uint32_t Bs = As + GM_BM * GM_LDA * 2;
        #pragma unroll
        for (int i = 0; i < 8; i++) {
            int u = tid + i * 256;
            if (i < 4) {
                int row = u >> 3, ch = u & 7;
                CP_ASYNC16(As + row * (GM_LDA * 2) + ch * 16,
                           Asrc + (size_t)row * KB + ch * 16);
            } else {
                int v = u - 1024;
                int row = v >> 3, ch = v & 7;
                CP_ASYNC16(Bs + row * (GM_LDA * 2) + ch * 16,
                           Bsrc + (size_t)row * KB + ch * 16);
            }
        }
        CP_ASYNC_COMMIT();
    };

    load_tile(0, 0);

    for (int c = 0; c < NCHUNK; c++) {
        if (c + 1 < NCHUNK) {
            load_tile((c + 1) & 1, c + 1);
            CP_ASYNC_WAIT1();
        } else {
            CP_ASYNC_WAIT0();
        }
        __syncthreads();

        uint32_t As = smem_base + (c & 1) * (GM_STAGE_ELEMS * 2);
        uint32_t Bs = As + GM_BM * GM_LDA * 2;
        uint32_t aAddr = As + aOff;
        uint32_t bAddr = Bs + bOff;

        #pragma unroll
        for (int kk = 0; kk < GM_BK; kk += 16) {
            uint32_t af[2][4], bfr[8][2];
            #pragma unroll
            for (int mi = 0; mi < 2; mi++)
                LDSM_X4(af[mi][0], af[mi][1], af[mi][2], af[mi][3],
                        aAddr + kk * 2 + mi * 16 * (GM_LDA * 2));
            #pragma unroll
            for (int pr = 0; pr < 4; pr++)
                LDSM_X4(bfr[2*pr][0], bfr[2*pr][1], bfr[2*pr+1][0], bfr[2*pr+1][1],
                        bAddr + kk * 2 + pr * 16 * (GM_LDA * 2));
            #pragma unroll
            for (int mi = 0; mi < 2; mi++)
                #pragma unroll
                for (int ni = 0; ni < 8; ni++)
                    mma16816(acc[mi][ni], af[mi], bfr[ni]);
        }
        __syncthreads();
    }

    // fused epilogue (all branches COALESCED)
    #pragma unroll
    for (int mi = 0; mi < 2; mi++) {
        int rowA = m0 + warpM * 32 + mi * 16 + g;
        #pragma unroll
        for (int ni = 0; ni < 8; ni++) {
            int col = n0 + warpN * 64 + ni * 8 + 2 * t4;
            #pragma unroll
            for (int half = 0; half < 2; half++) {
                int row = rowA + half * 8;
                float v0 = acc[mi][ni][half * 2 + 0];
                float v1 = acc[mi][ni][half * 2 + 1];
                if (mode == 0) {
                    *(float2*)(C + (size_t)row * N + col) =
                        make_float2(v0 + bias[col], v1 + bias[col + 1]);
                } else if (mode == 1) {
                    *(uint32_t*)(Cb + (size_t)row * N + col) = pack_bf16(v0, v1);
                } else {
                    size_t off = (size_t)row * N + col;
                    __nv_bfloat16 h0 = __float2bfloat16(v0);
                    __nv_bfloat16 h1 = __float2bfloat16(v1);
                    __nv_bfloat162 hp; hp.x = h0; hp.y = h1;
                    *(uint32_t*)(vrh + off) = *(uint32_t*)&hp;
                    *(uint32_t*)(vrl + off) =
                        pack_bf16(v0 - __bfloat162float(h0),
                                  v1 - __bfloat162float(h1));
                }
            }
        }
    }
}

// ---------------------------------------------------------------------------
// Flash attention on mma.sync, ldmatrix fragments, double-buffered K/V.
// (unchanged — numerics validated, rel_err 1.37e-4)
// ---------------------------------------------------------------------------
#define AT_LDQ 136
#define AT_LDK 136
#define AT_LDV 72
#define AT_ST_ELEMS (64*AT_LDK + 2*128*AT_LDV)
#define AT_SMEM ((128*AT_LDQ + 2*AT_ST_ELEMS) * 2)   // 143360 B

__global__ __launch_bounds__(256, 1)
void ca_attn_mma(const __nv_bfloat16* __restrict__ qb,
                 const __nv_bfloat16* __restrict__ kb,
                 const __nv_bfloat16* __restrict__ vth,
                 const __nv_bfloat16* __restrict__ vtl,
                 const float* __restrict__ sims,
                 const float* __restrict__ beta_p,
                 __nv_bfloat16* __restrict__ Oh,
                 __nv_bfloat16* __restrict__ Ol)
{
    extern __shared__ __align__(16) __nv_bfloat16 smattn[];
    const uint32_t sQ = smem_u32(smattn);

    const int qt = blockIdx.x, h = blockIdx.y, b = blockIdx.z;
    const int tid = threadIdx.x, wid = tid >> 5, lane = tid & 31;
    const int g = lane >> 2, t4 = lane & 3;
    const float beta = beta_p[0];
    const int qrow0 = b * N_ + qt * 128;
    const size_t vbase = (size_t)(b * HEADS_ + h) * HD_ * (size_t)L_;

    const uint32_t qOff = (uint32_t)(wid * 16 + (lane & 15)) * (AT_LDQ * 2)
                        + ((lane >> 4) << 3) * 2;
    const uint32_t kOff = (uint32_t)(((lane & 16) >> 1) + (lane & 7)) * (AT_LDK * 2)
                        + ((lane & 8) ? 16 : 0);
    const uint32_t vOff = (uint32_t)(((lane & 16) >> 1) + (lane & 7)) * (AT_LDV * 2)
                        + ((lane & 8) ? 16 : 0);

    #pragma unroll
    for (int i = 0; i < 8; i++) {
        int u = tid + i * 256, r = u >> 4, ch = u & 15;
        CP_ASYNC16(sQ + r * (AT_LDQ * 2) + ch * 16,
                   (const char*)qb + ((size_t)(qrow0 + r) * DIM_ + h * HD_) * 2 + ch * 16);
    }
    CP_ASYNC_COMMIT();

    auto stage_base = [&](int s) -> uint32_t {
        return sQ + 128 * AT_LDQ * 2 + s * (AT_ST_ELEMS * 2);
    };
    auto load_kv = [&](int s, int kt) {
        uint32_t sK  = stage_base(s);
        uint32_t sVh = sK + 64 * AT_LDK * 2;
        uint32_t sVl = sVh + 128 * AT_LDV * 2;
        const size_t krow0 = (size_t)(b * L_ + kt * 64);
        #pragma unroll
        for (int i = 0; i < 4; i++) {
            int u = tid + i * 256, r = u >> 4, ch = u & 15;
            CP_ASYNC16(sK + r * (AT_LDK * 2) + ch * 16,
                       (const char*)kb + ((krow0 + r) * DIM_ + h * HD_) * 2 + ch * 16);
        }
        #pragma unroll
        for (int i = 0; i < 4; i++) {
            int u = tid + i * 256, r = u >> 3, ch = u & 7;
            size_t src = (vbase + (size_t)r * L_ + kt * 64) * 2 + ch * 16;
            CP_ASYNC16(sVh + r * (AT_LDV * 2) + ch * 16, (const char*)vth + src);
        }
        #pragma unroll
        for (int i = 0; i < 4; i++) {
            int u = tid + i * 256, r = u >> 3, ch = u & 7;
            size_t src = (vbase + (size_t)r * L_ + kt * 64) * 2 + ch * 16;
            CP_ASYNC16(sVl + r * (AT_LDV * 2) + ch * 16, (const char*)vtl + src);
        }
        CP_ASYNC_COMMIT();
    };

    load_kv(0, 0);

    float o[16][4];
    #pragma unroll
    for (int nj = 0; nj < 16; nj++)
        #pragma unroll
        for (int r = 0; r < 4; r++) o[nj][r] = 0.f;
    float m0r = -3.0e38f, m1r = -3.0e38f, l0r = 0.f, l1r = 0.f;

    for (int kt = 0; kt < 64; kt++) {
        if (kt + 1 < 64) {
            load_kv((kt + 1) & 1, kt + 1);
            CP_ASYNC_WAIT1();
        } else {
            CP_ASYNC_WAIT0();
        }
        __syncthreads();

        uint32_t sK  = stage_base(kt & 1);
        uint32_t sVh = sK + 64 * AT_LDK * 2;
        uint32_t sVl = sVh + 128 * AT_LDV * 2;

        float s[8][4];
        #pragma unroll
        for (int nj = 0; nj < 8; nj++)
            #pragma unroll
            for (int r = 0; r < 4; r++) s[nj][r] = 0.f;

        #pragma unroll
        for (int kk = 0; kk < 128; kk += 16) {
            uint32_t af[4], bfr[8][2];
            LDSM_X4(af[0], af[1], af[2], af[3], sQ + qOff + kk * 2);
            #pragma unroll
            for (int pr = 0; pr < 4; pr++)
                LDSM_X4(bfr[2*pr][0], bfr[2*pr][1], bfr[2*pr+1][0], bfr[2*pr+1][1],
                        sK + kOff + kk * 2 + pr * 16 * (AT_LDK * 2));
            #pragma unroll
            for (int nj = 0; nj < 8; nj++)
                mma16816(s[nj], af, bfr[nj]);
        }

        const float simv = sims[b * M_DOCS + (kt >> 4)] * beta;
        float lg[8][4];
        float mt0 = -3.0e38f, mt1 = -3.0e38f;
        #pragma unroll
        for (int nj = 0; nj < 8; nj++) {
            lg[nj][0] = s[nj][0] * 0.03125f + simv;
            lg[nj][1] = s[nj][1] * 0.03125f + simv;
            lg[nj][2] = s[nj][2] * 0.03125f + simv;
            lg[nj][3] = s[nj][3] * 0.03125f + simv;
            mt0 = fmaxf(mt0, fmaxf(lg[nj][0], lg[nj][1]));
            mt1 = fmaxf(mt1, fmaxf(lg[nj][2], lg[nj][3]));
        }
        mt0 = fmaxf(mt0, __shfl_xor_sync(0xffffffffu, mt0, 1, 4));
        mt0 = fmaxf(mt0, __shfl_xor_sync(0xffffffffu, mt0, 2, 4));
        mt1 = fmaxf(mt1, __shfl_xor_sync(0xffffffffu, mt1, 1, 4));
        mt1 = fmaxf(mt1, __shfl_xor_sync(0xffffffffu, mt1, 2, 4));
        float mn0 = fmaxf(m0r, mt0), mn1 = fmaxf(m1r, mt1);
        float c0 = __expf(m0r - mn0), c1 = __expf(m1r - mn1);
        m0r = mn0; m1r = mn1; l0r *= c0; l1r *= c1;
        #pragma unroll
        for (int nj = 0; nj < 16; nj++) {
            o[nj][0] *= c0; o[nj][1] *= c0;
            o[nj][2] *= c1; o[nj][3] *= c1;
        }

        uint32_t ph01[8], ph23[8], pl01[8], pl23[8];
        #pragma unroll
        for (int nj = 0; nj < 8; nj++) {
            float p0 = __expf(lg[nj][0] - mn0), p1 = __expf(lg[nj][1] - mn0);
            float p2 = __expf(lg[nj][2] - mn1), p3 = __expf(lg[nj][3] - mn1);
            l0r += p0 + p1; l1r += p2 + p3;
            __nv_bfloat162 h01 = __float22bfloat162_rn(make_float2(p0, p1));
            __nv_bfloat162 h23 = __float22bfloat162_rn(make_float2(p2, p3));
            float2 b01 = __bfloat1622float2(h01);
            float2 b23 = __bfloat1622float2(h23);
            ph01[nj] = *(uint32_t*)&h01;
            ph23[nj] = *(uint32_t*)&h23;
            pl01[nj] = pack_bf16(p0 - b01.x, p1 - b01.y);
            pl23[nj] = pack_bf16(p2 - b23.x, p3 - b23.y);
        }

        #pragma unroll
        for (int kbi = 0; kbi < 4; kbi++) {
            uint32_t ah[4] = { ph01[2*kbi], ph23[2*kbi], ph01[2*kbi+1], ph23[2*kbi+1] };
            uint32_t al[4] = { pl01[2*kbi], pl23[2*kbi], pl01[2*kbi+1], pl23[2*kbi+1] };
            #pragma unroll
            for (int pr = 0; pr < 8; pr++) {
                uint32_t bh2[2], bh2b[2], bl2[2], bl2b[2];
                LDSM_X4(bh2[0], bh2[1], bh2b[0], bh2b[1],
                        sVh + vOff + kbi * 32 + pr * 16 * (AT_LDV * 2));
                LDSM_X4(bl2[0], bl2[1], bl2b[0], bl2b[1],
                        sVl + vOff + kbi * 32 + pr * 16 * (AT_LDV * 2));
                mma16816(o[2*pr],     ah, bh2);
                mma16816(o[2*pr],     ah, bl2);
                mma16816(o[2*pr],     al, bh2);
                mma16816(o[2*pr + 1], ah, bh2b);
                mma16816(o[2*pr + 1], ah, bl2b);
                mma16816(o[2*pr + 1], al, bh2b);
            }
        }
        __syncthreads();
    }

    l0r += __shfl_xor_sync(0xffffffffu, l0r, 1, 4);
    l0r += __shfl_xor_sync(0xffffffffu, l0r, 2, 4);
    l1r += __shfl_xor_sync(0xffffffffu, l1r, 1, 4);
    l1r += __shfl_xor_sync(0xffffffffu, l1r, 2, 4);
    float inv0 = 1.0f / l0r, inv1 = 1.0f / l1r;

    int row0 = qrow0 + wid * 16 + g;
    #pragma unroll
    for (int nj = 0; nj < 16; nj++) {
        int col = nj * 8 + 2 * t4;
        #pragma unroll
        for (int half = 0; half < 2; half++) {
            float v0 = o[nj][half * 2 + 0] * (half ? inv1 : inv0);
            float v1 = o[nj][half * 2 + 1] * (half ? inv1 : inv0);
            size_t off = (size_t)(row0 + half * 8) * DIM_ + h * HD_ + col;
            __nv_bfloat162 hi2;
            hi2.x = __float2bfloat16(v0);
            hi2.y = __float2bfloat16(v1);
            *(uint32_t*)(Oh + off) = *(uint32_t*)&hi2;
            *(uint32_t*)(Ol + off) =
                pack_bf16(v0 - __bfloat162float(hi2.x),
                          v1 - __bfloat162float(hi2.y));
        }
    }
}

// ---------------------------------------------------------------------------
extern "C" void kernel_launch(void* const* d_in, const int* in_sizes, int n_in,
                              void* d_out, int out_size)
{
    const float* x    = (const float*)d_in[0];
    const float* ctx  = (const float*)d_in[1];
    const float* sims = (const float*)d_in[2];
    const float* Wq   = (const float*)d_in[3];
    const float* Wkv  = (const float*)d_in[4];
    const float* beta = (const float*)d_in[5];
    const float* Wout = (const float*)d_in[6];
    const float* bout = (const float*)d_in[7];
    float* out = (float*)d_out;

    __nv_bfloat16 *xh, *xl, *ch, *cl, *oh, *ol;
    __nv_bfloat16 *wqh, *wql, *wkvh, *wkvl, *woh, *wol;
    __nv_bfloat16 *qb, *kbp, *vrh, *vrl, *vth, *vtl;
    cudaGetSymbolAddress((void**)&xh,  g_xh);
    cudaGetSymbolAddress((void**)&xl,  g_xl);
    cudaGetSymbolAddress((void**)&ch,  g_ch);
    cudaGetSymbolAddress((void**)&cl,  g_cl);
    cudaGetSymbolAddress((void**)&oh,  g_oh);
    cudaGetSymbolAddress((void**)&ol,  g_ol);
    cudaGetSymbolAddress((void**)&wqh, g_wqh);
    cudaGetSymbolAddress((void**)&wql, g_wql);
    cudaGetSymbolAddress((void**)&wkvh, g_wkvh);
    cudaGetSymbolAddress((void**)&wkvl, g_wkvl);
    cudaGetSymbolAddress((void**)&woh, g_woh);
    cudaGetSymbolAddress((void**)&wol, g_wol);
    cudaGetSymbolAddress((void**)&qb,  g_qb);
    cudaGetSymbolAddress((void**)&kbp, g_kb);
    cudaGetSymbolAddress((void**)&vrh, g_vrh);
    cudaGetSymbolAddress((void**)&vrl, g_vrl);
    cudaGetSymbolAddress((void**)&vth, g_vth);
    cudaGetSymbolAddress((void**)&vtl, g_vtl);

    cudaFuncSetAttribute(gemm_mma, cudaFuncAttributeMaxDynamicSharedMemorySize,
                         GM_SMEM_DYN);
    cudaFuncSetAttribute(ca_attn_mma, cudaFuncAttributeMaxDynamicSharedMemorySize,
                         AT_SMEM);

    // --- input conversions ---
    {
        int t1 = B_ * N_ * DIM_;
        conv_split<<<(t1 + 255) / 256, 256>>>(x, xh, xl, t1);
        int t2 = B_ * L_ * DIM_;
        conv_split<<<(t2 + 255) / 256, 256>>>(ctx, ch, cl, t2);
        conv_w_t<<<dim3(DIM_ / 32, DIM_ / 32), dim3(32, 8)>>>(Wq, wqh, wql,
                                                              DIM_, DIM_);
        conv_w_t<<<dim3((2 * DIM_) / 32, DIM_ / 32), dim3(32, 8)>>>(
            Wkv, wkvh, wkvl, DIM_, 2 * DIM_);
        conv_w_t<<<dim3(DIM_ / 32, DIM_ / 32), dim3(32, 8)>>>(Wout, woh, wol,
                                                              DIM_, DIM_);
    }

    // Q = x @ Wq -> qb (plain bf16), 1-PASS (Q consumed as bf16 anyway)
    gemm_mma<<<dim3(DIM_ / GM_BN, (B_ * N_) / GM_BM), 256, GM_SMEM_DYN>>>(
        xh, xl, wqh, wql, nullptr, nullptr, qb, nullptr, nullptr,
        B_ * N_, DIM_, DIM_, 1, 1);

    // K = ctx @ Wkv[:, :1024] -> kb (plain bf16), 1-PASS (K consumed as bf16)
    gemm_mma<<<dim3(DIM_ / GM_BN, (B_ * L_) / GM_BM), 256, GM_SMEM_DYN>>>(
        ch, cl, wkvh, wkvl, nullptr, nullptr, kbp, nullptr, nullptr,
        B_ * L_, DIM_, DIM_, 1, 1);

    // V = ctx @ Wkv[:, 1024:] -> vrh/vrl (split row-major), 3-PASS
    gemm_mma<<<dim3(DIM_ / GM_BN, (B_ * L_) / GM_BM), 256, GM_SMEM_DYN>>>(
        ch, cl, wkvh + (size_t)DIM_ * DIM_, wkvl + (size_t)DIM_ * DIM_,
        nullptr, nullptr, nullptr, vrh, vrl,
        B_ * L_, DIM_, DIM_, 2, 3);

    // transpose V hi+lo in one launch (coalesced both sides)
    vt_trans2<<<dim3(L_ / 32, DIM_ / 32, B_), dim3(32, 8)>>>(vrh, vrl, vth, vtl);

    // attention -> oh/ol (split bf16, fused)
    ca_attn_mma<<<dim3(N_ / 128, HEADS_, B_), 256, AT_SMEM>>>(
        qb, kbp, vth, vtl, sims, beta, oh, ol);

    // out = O @ Wout + bout (fp32), 3-PASS
    gemm_mma<<<dim3(DIM_ / GM_BN, (B_ * N_) / GM_BM), 256, GM_SMEM_DYN>>>(
        oh, ol, woh, wol, bout, out, nullptr, nullptr, nullptr,
        B_ * N_, DIM_, DIM_, 0, 3);
}

// round 14
// speedup vs baseline: 1.9802x; 1.1239x over previous
#include <cuda_runtime.h>
#include <cuda_bf16.h>
#include <math.h>
#include <stdint.h>

// Problem constants
#define B_     2
#define N_     1024
#define DIM_   1024
#define HEADS_ 8
#define HD_    128
#define L_     4096   // m * nc
#define M_DOCS 4

// ---------------------------------------------------------------------------
// Scratch (__device__ globals; allocation-free rule)
// ---------------------------------------------------------------------------
__device__ __nv_bfloat16 g_xh [(B_*N_) * DIM_];
__device__ __nv_bfloat16 g_xl [(B_*N_) * DIM_];
__device__ __nv_bfloat16 g_ch [(B_*L_) * DIM_];
__device__ __nv_bfloat16 g_cl [(B_*L_) * DIM_];
__device__ __nv_bfloat16 g_oh [(B_*N_) * DIM_];   // attn output, split hi
__device__ __nv_bfloat16 g_ol [(B_*N_) * DIM_];   // attn output, split lo
// weights transposed to [N,K]
__device__ __nv_bfloat16 g_wqh [DIM_ * DIM_];
__device__ __nv_bfloat16 g_wql [DIM_ * DIM_];
__device__ __nv_bfloat16 g_wkvh[(2*DIM_) * DIM_];
__device__ __nv_bfloat16 g_wkvl[(2*DIM_) * DIM_];
__device__ __nv_bfloat16 g_woh [DIM_ * DIM_];
__device__ __nv_bfloat16 g_wol [DIM_ * DIM_];

// attention operands
__device__ __nv_bfloat16 g_qb [(B_*N_) * DIM_];   // Q plain bf16
__device__ __nv_bfloat16 g_kb [(B_*L_) * DIM_];   // K plain bf16
__device__ __nv_bfloat16 g_vrh[(B_*L_) * DIM_];   // V row-major hi
__device__ __nv_bfloat16 g_vrl[(B_*L_) * DIM_];   // V row-major lo

// ---------------------------------------------------------------------------
// PTX helpers — ONLY non-'a' features (compute_103 PTX: no tcgen05).
// ---------------------------------------------------------------------------
#define CP_ASYNC16(dst, src) \
    asm volatile("cp.async.cg.shared.global [%0], [%1], 16;\n" \
                 :: "r"(dst), "l"(src) : "memory")
#define CP_ASYNC_COMMIT()  asm volatile("cp.async.commit_group;\n" ::: "memory")
#define CP_ASYNC_WAIT1()   asm volatile("cp.async.wait_group 1;\n" ::: "memory")
#define CP_ASYNC_WAIT0()   asm volatile("cp.async.wait_group 0;\n" ::: "memory")

#define LDSM_X4(r0, r1, r2, r3, a) \
    asm volatile("ldmatrix.sync.aligned.m8n8.x4.shared.b16 {%0,%1,%2,%3}, [%4];" \
                 : "=r"(r0), "=r"(r1), "=r"(r2), "=r"(r3) : "r"(a))

#define LDSM_X4_T(r0, r1, r2, r3, a) \
    asm volatile("ldmatrix.sync.aligned.m8n8.x4.trans.shared.b16 {%0,%1,%2,%3}, [%4];" \
                 : "=r"(r0), "=r"(r1), "=r"(r2), "=r"(r3) : "r"(a))

__device__ __forceinline__ uint32_t smem_u32(const void* p) {
    uint32_t a;
    asm("{ .reg .u64 t; cvta.to.shared.u64 t, %1; cvt.u32.u64 %0, t; }"
        : "=r"(a) : "l"(p));
    return a;
}

// D += A @ B^T : m16n8k16, bf16 in, fp32 accum (layout validated R8/R10)
__device__ __forceinline__ void mma16816(float* d, const uint32_t* a,
                                         const uint32_t* b) {
    asm volatile(
        "mma.sync.aligned.m16n8k16.row.col.f32.bf16.bf16.f32 "
        "{%0,%1,%2,%3}, {%4,%5,%6,%7}, {%8,%9}, {%0,%1,%2,%3};"
        : "+f"(d[0]), "+f"(d[1]), "+f"(d[2]), "+f"(d[3])
        : "r"(a[0]), "r"(a[1]), "r"(a[2]), "r"(a[3]), "r"(b[0]), "r"(b[1]));
}

__device__ __forceinline__ uint32_t pack_bf16(float a, float b) {
    __nv_bfloat162 t = __float22bfloat162_rn(make_float2(a, b));
    return *(uint32_t*)&t;
}

// ---------------------------------------------------------------------------
// Conversion kernels (inputs + weights only)
// ---------------------------------------------------------------------------
__global__ void conv_split(const float* __restrict__ A,
                           __nv_bfloat16* __restrict__ Ah,
                           __nv_bfloat16* __restrict__ Al, int total)
{
    int i = blockIdx.x * blockDim.x + threadIdx.x;
    if (i >= total) return;
    float v = A[i];
    __nv_bfloat16 hi = __float2bfloat16(v);
    Ah[i] = hi;
    Al[i] = __float2bfloat16(v - __bfloat162float(hi));
}

// W[K,N] fp32 -> Wh/Wl [N,K] bf16 (transpose + split)
__global__ void conv_w_t(const float* __restrict__ W,
                         __nv_bfloat16* __restrict__ Wh,
                         __nv_bfloat16* __restrict__ Wl, int K, int N)
{
    __shared__ float t[32][33];
    int k0 = blockIdx.y * 32, n0 = blockIdx.x * 32;
    int tx = threadIdx.x, ty = threadIdx.y;
    #pragma unroll
    for (int i = 0; i < 32; i += 8)
        t[ty + i][tx] = W[(size_t)(k0 + ty + i) * N + n0 + tx];
    __syncthreads();
    #pragma unroll
    for (int i = 0; i < 32; i += 8) {
        float v = t[tx][ty + i];
        __nv_bfloat16 hi = __float2bfloat16(v);
        size_t o = (size_t)(n0 + ty + i) * K + k0 + tx;
        Wh[o] = hi;
        Wl[o] = __float2bfloat16(v - __bfloat162float(hi));
    }
}

// ---------------------------------------------------------------------------
// GEMM core (shared by fused QKV launch and the out-GEMM launch)
//   npasses: 1 = plain bf16, 3 = split
//   mode 0: C fp32 = acc + bias;  mode 1: Cb bf16;  mode 2: split to vrh/vrl
// ---------------------------------------------------------------------------
#define GM_BM  128
#define GM_BN  128
#define GM_BK  64
#define GM_LDA 72
#define GM_STAGE_ELEMS ((GM_BM + GM_BN) * GM_LDA)
#define GM_SMEM_DYN (2 * GM_STAGE_ELEMS * 2)

__device__ __forceinline__ void gemm_core(
    const __nv_bfloat16* __restrict__ Ah, const __nv_bfloat16* __restrict__ Al,
    const __nv_bfloat16* __restrict__ Bh, const __nv_bfloat16* __restrict__ Bl,
    const float* __restrict__ bias, float* __restrict__ C,
    __nv_bfloat16* __restrict__ Cb,
    __nv_bfloat16* __restrict__ vrh, __nv_bfloat16* __restrict__ vrl,
    int M, int N, int K, int mode, int npasses, int m0, int n0,
    __nv_bfloat16* dsm)
{
    const int tid   = threadIdx.x;
    const int wid   = tid >> 5;
    const int lane  = tid & 31;
    const int g     = lane >> 2;
    const int t4    = lane & 3;
    const int warpM = wid & 3;
    const int warpN = wid >> 2;
    const int KB = K * 2;
    const int kchunks = K / GM_BK;
    const int NCHUNK = npasses * kchunks;

    const uint32_t smem_base = smem_u32(dsm);

    const uint32_t aOff = (uint32_t)(warpM * 32 + (lane & 15)) * (GM_LDA * 2)
                        + ((lane >> 4) << 3) * 2;
    const uint32_t bOff = (uint32_t)(warpN * 64 + ((lane & 16) >> 1) + (lane & 7))
                        * (GM_LDA * 2) + ((lane & 8) ? 16 : 0);

    float acc[2][8][4];
    #pragma unroll
    for (int mi = 0; mi < 2; mi++)
        #pragma unroll
        for (int ni = 0; ni < 8; ni++)
            #pragma unroll
            for (int r = 0; r < 4; r++) acc[mi][ni][r] = 0.f;

    auto load_tile = [&](int s, int c) {
        int pass = c / kchunks;
        int kc   = c - pass * kchunks;
        const char* Asrc = (const char*)((pass < 2) ? Ah : Al)
                         + (size_t)m0 * KB + (size_t)kc * (GM_BK * 2);
        const char* Bsrc = (const char*)((pass == 1) ? Bl : Bh)
                         + (size_t)n0 * KB + (size_t)kc * (GM_BK * 2);
        uint32_t As = smem_base + s * (GM_STAGE_ELEMS * 2);
        uint32_t Bs = As + GM_BM * GM_LDA * 2;
        #pragma unroll
        for (int i = 0; i < 8; i++) {
            int u = tid + i * 256;
            if (i < 4) {
                int row = u >> 3, ch = u & 7;
                CP_ASYNC16(As + row * (GM_LDA * 2) + ch * 16,
                           Asrc + (size_t)row * KB + ch * 16);
            } else {
                int v = u - 1024;
                int row = v >> 3, ch = v & 7;
                CP_ASYNC16(Bs + row * (GM_LDA * 2) + ch * 16,
                           Bsrc + (size_t)row * KB + ch * 16);
            }
        }
        CP_ASYNC_COMMIT();
    };

    load_tile(0, 0);

    for (int c = 0; c < NCHUNK; c++) {
        if (c + 1 < NCHUNK) {
            load_tile((c + 1) & 1, c + 1);
            CP_ASYNC_WAIT1();
        } else {
            CP_ASYNC_WAIT0();
        }
        __syncthreads();

        uint32_t As = smem_base + (c & 1) * (GM_STAGE_ELEMS * 2);
        uint32_t Bs = As + GM_BM * GM_LDA * 2;
        uint32_t aAddr = As + aOff;
        uint32_t bAddr = Bs + bOff;

        #pragma unroll
        for (int kk = 0; kk < GM_BK; kk += 16) {
            uint32_t af[2][4], bfr[8][2];
            #pragma unroll
            for (int mi = 0; mi < 2; mi++)
                LDSM_X4(af[mi][0], af[mi][1], af[mi][2], af[mi][3],
                        aAddr + kk * 2 + mi * 16 * (GM_LDA * 2));
            #pragma unroll
            for (int pr = 0; pr < 4; pr++)
                LDSM_X4(bfr[2*pr][0], bfr[2*pr][1], bfr[2*pr+1][0], bfr[2*pr+1][1],
                        bAddr + kk * 2 + pr * 16 * (GM_LDA * 2));
            #pragma unroll
            for (int mi = 0; mi < 2; mi++)
                #pragma unroll
                for (int ni = 0; ni < 8; ni++)
                    mma16816(acc[mi][ni], af[mi], bfr[ni]);
        }
        __syncthreads();
    }

    // fused epilogue (all branches COALESCED)
    #pragma unroll
    for (int mi = 0; mi < 2; mi++) {
        int rowA = m0 + warpM * 32 + mi * 16 + g;
        #pragma unroll
        for (int ni = 0; ni < 8; ni++) {
            int col = n0 + warpN * 64 + ni * 8 + 2 * t4;
            #pragma unroll
            for (int half = 0; half < 2; half++) {
                int row = rowA + half * 8;
                float v0 = acc[mi][ni][half * 2 + 0];
                float v1 = acc[mi][ni][half * 2 + 1];
                if (mode == 0) {
                    *(float2*)(C + (size_t)row * N + col) =
                        make_float2(v0 + bias[col], v1 + bias[col + 1]);
                } else if (mode == 1) {
                    *(uint32_t*)(Cb + (size_t)row * N + col) = pack_bf16(v0, v1);
                } else {
                    size_t off = (size_t)row * N + col;
                    __nv_bfloat16 h0 = __float2bfloat16(v0);
                    __nv_bfloat16 h1 = __float2bfloat16(v1);
                    __nv_bfloat162 hp; hp.x = h0; hp.y = h1;
                    *(uint32_t*)(vrh + off) = *(uint32_t*)&hp;
                    *(uint32_t*)(vrl + off) =
                        pack_bf16(v0 - __bfloat162float(h0),
                                  v1 - __bfloat162float(h1));
                }
            }
        }
    }
}

// standalone GEMM (out-projection)
__global__ __launch_bounds__(256, 2)
void gemm_mma(const __nv_bfloat16* __restrict__ Ah,
              const __nv_bfloat16* __restrict__ Al,
              const __nv_bfloat16* __restrict__ Bh,
              const __nv_bfloat16* __restrict__ Bl,
              const float* __restrict__ bias, float* __restrict__ C,
              int M, int N, int K, int npasses)
{
    extern __shared__ __align__(16) __nv_bfloat16 dsm[];
    gemm_core(Ah, Al, Bh, Bl, bias, C, nullptr, nullptr, nullptr,
              M, N, K, 0, npasses, blockIdx.y * GM_BM, blockIdx.x * GM_BN, dsm);
}

// fused Q + K + V GEMMs, one launch (1152 CTAs; V first — longest per-CTA)
__global__ __launch_bounds__(256, 2)
void gemm_qkv(const __nv_bfloat16* __restrict__ xh,
              const __nv_bfloat16* __restrict__ xl,
              const __nv_bfloat16* __restrict__ ch,
              const __nv_bfloat16* __restrict__ cl,
              const __nv_bfloat16* __restrict__ wqh,
              const __nv_bfloat16* __restrict__ wql,
              const __nv_bfloat16* __restrict__ wkvh,
              const __nv_bfloat16* __restrict__ wkvl,
              __nv_bfloat16* __restrict__ qb,
              __nv_bfloat16* __restrict__ kb,
              __nv_bfloat16* __restrict__ vrh,
              __nv_bfloat16* __restrict__ vrl)
{
    extern __shared__ __align__(16) __nv_bfloat16 dsm[];
    int id = blockIdx.x;
    if (id < 512) {                     // V: 3-pass, split row-major out
        int m0 = (id >> 3) * GM_BM, n0 = (id & 7) * GM_BN;
        gemm_core(ch, cl, wkvh + (size_t)DIM_ * DIM_, wkvl + (size_t)DIM_ * DIM_,
                  nullptr, nullptr, nullptr, vrh, vrl,
                  B_ * L_, DIM_, DIM_, 2, 3, m0, n0, dsm);
    } else if (id < 1024) {             // K: 1-pass, plain bf16
        int t = id - 512;
        int m0 = (t >> 3) * GM_BM, n0 = (t & 7) * GM_BN;
        gemm_core(ch, cl, wkvh, wkvl, nullptr, nullptr, kb, nullptr, nullptr,
                  B_ * L_, DIM_, DIM_, 1, 1, m0, n0, dsm);
    } else {                            // Q: 1-pass, plain bf16
        int t = id - 1024;
        int m0 = (t >> 3) * GM_BM, n0 = (t & 7) * GM_BN;
        gemm_core(xh, xl, wqh, wql, nullptr, nullptr, qb, nullptr, nullptr,
                  B_ * N_, DIM_, DIM_, 1, 1, m0, n0, dsm);
    }
}

// ---------------------------------------------------------------------------
// Flash attention on mma.sync.  V loaded ROW-MAJOR ([64 keys][128 d]) and
// transposed on delivery via ldmatrix.trans — vt_trans kernel eliminated.
// ---------------------------------------------------------------------------
#define AT_LDQ 136
#define AT_LDK 136
#define AT_LDV 136                                  // V row-major: 128 d + pad
#define AT_ST_ELEMS (64*AT_LDK + 2*64*AT_LDV)       // K + Vh + Vl per stage
#define AT_SMEM ((128*AT_LDQ + 2*AT_ST_ELEMS) * 2)  // 139264 B

__global__ __launch_bounds__(256, 1)
void ca_attn_mma(const __nv_bfloat16* __restrict__ qb,
                 const __nv_bfloat16* __restrict__ kb,
                 const __nv_bfloat16* __restrict__ vrh,
                 const __nv_bfloat16* __restrict__ vrl,
                 const float* __restrict__ sims,
                 const float* __restrict__ beta_p,
                 __nv_bfloat16* __restrict__ Oh,
                 __nv_bfloat16* __restrict__ Ol)
{
    extern __shared__ __align__(16) __nv_bfloat16 smattn[];
    const uint32_t sQ = smem_u32(smattn);

    const int qt = blockIdx.x, h = blockIdx.y, b = blockIdx.z;
    const int tid = threadIdx.x, wid = tid >> 5, lane = tid & 31;
    const int g = lane >> 2, t4 = lane & 3;
    const float beta = beta_p[0];
    const int qrow0 = b * N_ + qt * 128;

    const uint32_t qOff = (uint32_t)(wid * 16 + (lane & 15)) * (AT_LDQ * 2)
                        + ((lane >> 4) << 3) * 2;
    const uint32_t kOff = (uint32_t)(((lane & 16) >> 1) + (lane & 7)) * (AT_LDK * 2)
                        + ((lane & 8) ? 16 : 0);
    // trans-ldmatrix V lane offset: key row from (lane&8), d-halftile from (lane&16)
    const uint32_t vOffT = (uint32_t)(((lane & 8) ? 8 : 0) + (lane & 7)) * (AT_LDV * 2)
                         + ((lane & 16) ? 16 : 0);

    #pragma unroll
    for (int i = 0; i < 8; i++) {
        int u = tid + i * 256, r = u >> 4, ch = u & 15;
        CP_ASYNC16(sQ + r * (AT_LDQ * 2) + ch * 16,
                   (const char*)qb + ((size_t)(qrow0 + r) * DIM_ + h * HD_) * 2 + ch * 16);
    }
    CP_ASYNC_COMMIT();

    auto stage_base = [&](int s) -> uint32_t {
        return sQ + 128 * AT_LDQ * 2 + s * (AT_ST_ELEMS * 2);
    };
    auto load_kv = [&](int s, int kt) {
        uint32_t sK  = stage_base(s);
        uint32_t sVh = sK + 64 * AT_LDK * 2;
        uint32_t sVl = sVh + 64 * AT_LDV * 2;
        const size_t krow0 = (size_t)(b * L_ + kt * 64);
        #pragma unroll
        for (int i = 0; i < 4; i++) {
            int u = tid + i * 256, r = u >> 4, ch = u & 15;
            CP_ASYNC16(sK + r * (AT_LDK * 2) + ch * 16,
                       (const char*)kb + ((krow0 + r) * DIM_ + h * HD_) * 2 + ch * 16);
        }
        #pragma unroll
        for (int i = 0; i < 4; i++) {     // V hi: 64 rows x 256 B, row-major
            int u = tid + i * 256, r = u >> 4, ch = u & 15;
            CP_ASYNC16(sVh + r * (AT_LDV * 2) + ch * 16,
                       (const char*)vrh + ((krow0 + r) * DIM_ + h * HD_) * 2 + ch * 16);
        }
        #pragma unroll
        for (int i = 0; i < 4; i++) {     // V lo
            int u = tid + i * 256, r = u >> 4, ch = u & 15;
            CP_ASYNC16(sVl + r * (AT_LDV * 2) + ch * 16,
                       (const char*)vrl + ((krow0 + r) * DIM_ + h * HD_) * 2 + ch * 16);
        }
        CP_ASYNC_COMMIT();
    };

    load_kv(0, 0);

    float o[16][4];
    #pragma unroll
    for (int nj = 0; nj < 16; nj++)
        #pragma unroll
        for (int r = 0; r < 4; r++) o[nj][r] = 0.f;
    float m0r = -3.0e38f, m1r = -3.0e38f, l0r = 0.f, l1r = 0.f;

    for (int kt = 0; kt < 64; kt++) {
        if (kt + 1 < 64) {
            load_kv((kt + 1) & 1, kt + 1);
            CP_ASYNC_WAIT1();
        } else {
            CP_ASYNC_WAIT0();
        }
        __syncthreads();

        uint32_t sK  = stage_base(kt & 1);
        uint32_t sVh = sK + 64 * AT_LDK * 2;
        uint32_t sVl = sVh + 64 * AT_LDV * 2;

        // ---- S = Q @ K^T ----
        float s[8][4];
        #pragma unroll
        for (int nj = 0; nj < 8; nj++)
            #pragma unroll
            for (int r = 0; r < 4; r++) s[nj][r] = 0.f;

        #pragma unroll
        for (int kk = 0; kk < 128; kk += 16) {
            uint32_t af[4], bfr[8][2];
            LDSM_X4(af[0], af[1], af[2], af[3], sQ + qOff + kk * 2);
            #pragma unroll
            for (int pr = 0; pr < 4; pr++)
                LDSM_X4(bfr[2*pr][0], bfr[2*pr][1], bfr[2*pr+1][0], bfr[2*pr+1][1],
                        sK + kOff + kk * 2 + pr * 16 * (AT_LDK * 2));
            #pragma unroll
            for (int nj = 0; nj < 8; nj++)
                mma16816(s[nj], af, bfr[nj]);
        }

        // ---- online softmax ----
        const float simv = sims[b * M_DOCS + (kt >> 4)] * beta;
        float lg[8][4];
        float mt0 = -3.0e38f, mt1 = -3.0e38f;
        #pragma unroll
        for (int nj = 0; nj < 8; nj++) {
            lg[nj][0] = s[nj][0] * 0.03125f + simv;
            lg[nj][1] = s[nj][1] * 0.03125f + simv;
            lg[nj][2] = s[nj][2] * 0.03125f + simv;
            lg[nj][3] = s[nj][3] * 0.03125f + simv;
            mt0 = fmaxf(mt0, fmaxf(lg[nj][0], lg[nj][1]));
            mt1 = fmaxf(mt1, fmaxf(lg[nj][2], lg[nj][3]));
        }
        mt0 = fmaxf(mt0, __shfl_xor_sync(0xffffffffu, mt0, 1, 4));
        mt0 = fmaxf(mt0, __shfl_xor_sync(0xffffffffu, mt0, 2, 4));
        mt1 = fmaxf(mt1, __shfl_xor_sync(0xffffffffu, mt1, 1, 4));
        mt1 = fmaxf(mt1, __shfl_xor_sync(0xffffffffu, mt1, 2, 4));
        float mn0 = fmaxf(m0r, mt0), mn1 = fmaxf(m1r, mt1);
        float c0 = __expf(m0r - mn0), c1 = __expf(m1r - mn1);
        m0r = mn0; m1r = mn1; l0r *= c0; l1r *= c1;
        #pragma unroll
        for (int nj = 0; nj < 16; nj++) {
            o[nj][0] *= c0; o[nj][1] *= c0;
            o[nj][2] *= c1; o[nj][3] *= c1;
        }

        uint32_t ph01[8], ph23[8], pl01[8], pl23[8];
        #pragma unroll
        for (int nj = 0; nj < 8; nj++) {
            float p0 = __expf(lg[nj][0] - mn0), p1 = __expf(lg[nj][1] - mn0);
            float p2 = __expf(lg[nj][2] - mn1), p3 = __expf(lg[nj][3] - mn1);
            l0r += p0 + p1; l1r += p2 + p3;
            __nv_bfloat162 h01 = __float22bfloat162_rn(make_float2(p0, p1));
            __nv_bfloat162 h23 = __float22bfloat162_rn(make_float2(p2, p3));
            float2 b01 = __bfloat1622float2(h01);
            float2 b23 = __bfloat1622float2(h23);
            ph01[nj] = *(uint32_t*)&h01;
            ph23[nj] = *(uint32_t*)&h23;
            pl01[nj] = pack_bf16(p0 - b01.x, p1 - b01.y);
            pl23[nj] = pack_bf16(p2 - b23.x, p3 - b23.y);
        }

        // ---- O += ph*Vh + ph*Vl + pl*Vh  (V fragments via ldmatrix.trans) ----
        #pragma unroll
        for (int kbi = 0; kbi < 4; kbi++) {
            uint32_t ah[4] = { ph01[2*kbi], ph23[2*kbi], ph01[2*kbi+1], ph23[2*kbi+1] };
            uint32_t al[4] = { pl01[2*kbi], pl23[2*kbi], pl01[2*kbi+1], pl23[2*kbi+1] };
            #pragma unroll
            for (int pr = 0; pr < 8; pr++) {
                uint32_t bh2[2], bh2b[2], bl2[2], bl2b[2];
                uint32_t adrH = sVh + vOffT + (kbi * 16) * (AT_LDV * 2) + pr * 32;
                uint32_t adrL = sVl + vOffT + (kbi * 16) * (AT_LDV * 2) + pr * 32;
                LDSM_X4_T(bh2[0], bh2[1], bh2b[0], bh2b[1], adrH);
                LDSM_X4_T(bl2[0], bl2[1], bl2b[0], bl2b[1], adrL);
                mma16816(o[2*pr],     ah, bh2);
                mma16816(o[2*pr],     ah, bl2);
                mma16816(o[2*pr],     al, bh2);
                mma16816(o[2*pr + 1], ah, bh2b);
                mma16816(o[2*pr + 1], ah, bl2b);
                mma16816(o[2*pr + 1], al, bh2b);
            }
        }
        __syncthreads();
    }

    l0r += __shfl_xor_sync(0xffffffffu, l0r, 1, 4);
    l0r += __shfl_xor_sync(0xffffffffu, l0r, 2, 4);
    l1r += __shfl_xor_sync(0xffffffffu, l1r, 1, 4);
    l1r += __shfl_xor_sync(0xffffffffu, l1r, 2, 4);
    float inv0 = 1.0f / l0r, inv1 = 1.0f / l1r;

    int row0 = qrow0 + wid * 16 + g;
    #pragma unroll
    for (int nj = 0; nj < 16; nj++) {
        int col = nj * 8 + 2 * t4;
        #pragma unroll
        for (int half = 0; half < 2; half++) {
            float v0 = o[nj][half * 2 + 0] * (half ? inv1 : inv0);
            float v1 = o[nj][half * 2 + 1] * (half ? inv1 : inv0);
            size_t off = (size_t)(row0 + half * 8) * DIM_ + h * HD_ + col;
            __nv_bfloat162 hi2;
            hi2.x = __float2bfloat16(v0);
            hi2.y = __float2bfloat16(v1);
            *(uint32_t*)(Oh + off) = *(uint32_t*)&hi2;
            *(uint32_t*)(Ol + off) =
                pack_bf16(v0 - __bfloat162float(hi2.x),
                          v1 - __bfloat162float(hi2.y));
        }
    }
}

// ---------------------------------------------------------------------------
extern "C" void kernel_launch(void* const* d_in, const int* in_sizes, int n_in,
                              void* d_out, int out_size)
{
    const float* x    = (const float*)d_in[0];
    const float* ctx  = (const float*)d_in[1];
    const float* sims = (const float*)d_in[2];
    const float* Wq   = (const float*)d_in[3];
    const float* Wkv  = (const float*)d_in[4];
    const float* beta = (const float*)d_in[5];
    const float* Wout = (const float*)d_in[6];
    const float* bout = (const float*)d_in[7];
    float* out = (float*)d_out;

    __nv_bfloat16 *xh, *xl, *ch, *cl, *oh, *ol;
    __nv_bfloat16 *wqh, *wql, *wkvh, *wkvl, *woh, *wol;
    __nv_bfloat16 *qb, *kbp, *vrh, *vrl;
    cudaGetSymbolAddress((void**)&xh,  g_xh);
    cudaGetSymbolAddress((void**)&xl,  g_xl);
    cudaGetSymbolAddress((void**)&ch,  g_ch);
    cudaGetSymbolAddress((void**)&cl,  g_cl);
    cudaGetSymbolAddress((void**)&oh,  g_oh);
    cudaGetSymbolAddress((void**)&ol,  g_ol);
    cudaGetSymbolAddress((void**)&wqh, g_wqh);
    cudaGetSymbolAddress((void**)&wql, g_wql);
    cudaGetSymbolAddress((void**)&wkvh, g_wkvh);
    cudaGetSymbolAddress((void**)&wkvl, g_wkvl);
    cudaGetSymbolAddress((void**)&woh, g_woh);
    cudaGetSymbolAddress((void**)&wol, g_wol);
    cudaGetSymbolAddress((void**)&qb,  g_qb);
    cudaGetSymbolAddress((void**)&kbp, g_kb);
    cudaGetSymbolAddress((void**)&vrh, g_vrh);
    cudaGetSymbolAddress((void**)&vrl, g_vrl);

    cudaFuncSetAttribute(gemm_mma, cudaFuncAttributeMaxDynamicSharedMemorySize,
                         GM_SMEM_DYN);
    cudaFuncSetAttribute(gemm_qkv, cudaFuncAttributeMaxDynamicSharedMemorySize,
                         GM_SMEM_DYN);
    cudaFuncSetAttribute(ca_attn_mma, cudaFuncAttributeMaxDynamicSharedMemorySize,
                         AT_SMEM);

    // --- input conversions ---
    {
        int t1 = B_ * N_ * DIM_;
        conv_split<<<(t1 + 255) / 256, 256>>>(x, xh, xl, t1);
        int t2 = B_ * L_ * DIM_;
        conv_split<<<(t2 + 255) / 256, 256>>>(ctx, ch, cl, t2);
        conv_w_t<<<dim3(DIM_ / 32, DIM_ / 32), dim3(32, 8)>>>(Wq, wqh, wql,
                                                              DIM_, DIM_);
        conv_w_t<<<dim3((2 * DIM_) / 32, DIM_ / 32), dim3(32, 8)>>>(
            Wkv, wkvh, wkvl, DIM_, 2 * DIM_);
        conv_w_t<<<dim3(DIM_ / 32, DIM_ / 32), dim3(32, 8)>>>(Wout, woh, wol,
                                                              DIM_, DIM_);
    }

    // Q + K + V GEMMs fused into one launch (V 3-pass first for load balance)
    gemm_qkv<<<1152, 256, GM_SMEM_DYN>>>(xh, xl, ch, cl, wqh, wql, wkvh, wkvl,
                                         qb, kbp, vrh, vrl);

    // attention -> oh/ol (split bf16; V transposed in-register via ldmatrix.trans)
    ca_attn_mma<<<dim3(N_ / 128, HEADS_, B_), 256, AT_SMEM>>>(
        qb, kbp, vrh, vrl, sims, beta, oh, ol);

    // out = O @ Wout + bout (fp32), 3-PASS
    gemm_mma<<<dim3(DIM_ / GM_BN, (B_ * N_) / GM_BM), 256, GM_SMEM_DYN>>>(
        oh, ol, woh, wol, bout, out, B_ * N_, DIM_, DIM_, 3);
}